// round 3
// baseline (speedup 1.0000x reference)
#include <cuda_runtime.h>
#include <cuda_bf16.h>

#define B_   512
#define N_   50
#define D_   128
#define H_   200
#define E_   50000
#define KPAD 208            // H_ padded to 13*16 for mma
#define KU   (KPAD/2)       // 104 uints per row
#define GBM  128
#define GBN  128
#define NPART 391           // ceil(E_/GBN)
#define SAS  216            // padded bf16 smem stride

// ---------------- static device scratch ----------------
__device__ __nv_bfloat16 g_wb[E_ * KPAD];   // mlp_w bf16, K-padded
__device__ __nv_bfloat16 g_vb[B_ * KPAD];   // poses bf16, K-padded
__device__ float g_v[B_ * H_];              // poses fp32 (for fixdot)
__device__ float g_part[B_ * NPART];        // per-(row, e-block) partial sum(exp)
__device__ float g_invZs[B_];               // 0.5 / Z_s
__device__ float g_pbase[B_];               // 0.5 * exp(-m_p) / Z_p
__device__ float g_fix_p[B_ * N_];          // p-term then final value per distinct id
__device__ int   g_fix_id[B_ * N_];
__device__ int   g_fix_cnt[B_];

// ---------------- K0: mlp_w fp32 -> bf16 padded (vectorized) ----------------
__global__ void k_convert(const float* __restrict__ w) {
    int i = blockIdx.x * 256 + threadIdx.x;        // uint2 (4 bf16) index
    if (i >= E_ * 52) return;
    int e = i / 52, q = i - e * 52;
    uint2 val;
    if (q < 50) {
        float4 f = *(const float4*)(w + (size_t)e * H_ + 4 * q);
        __nv_bfloat162 lo = __floats2bfloat162_rn(f.x, f.y);
        __nv_bfloat162 hi = __floats2bfloat162_rn(f.z, f.w);
        val.x = *(unsigned*)&lo;
        val.y = *(unsigned*)&hi;
    } else {
        val.x = 0u; val.y = 0u;
    }
    ((uint2*)g_wb)[(size_t)e * 52 + q] = val;
}

// ---------------- K1: gather + projection + routing (one block/row, 512 thr) ----------------
#define SW_STR 129
#define ROUT_SMEM ((200 * SW_STR + 50 * 128 + 50 * 200 + 50 + 50 + 200 + 50 + 17 + 50) * 4)

__global__ void __launch_bounds__(512) k_routing(
    const int* __restrict__ idx, const int* __restrict__ times,
    const float* __restrict__ emb, const float* __restrict__ Ws_w,
    const float* __restrict__ Ws_b)
{
    extern __shared__ float sm[];
    float* sW  = sm;                    // [200][129]
    float* sE  = sW + 200 * SW_STR;     // [50][128]
    float* sU  = sE + 50 * 128;         // [50][200]
    float* sB  = sU + 50 * 200;         // [50]
    float* sC  = sB + 50;               // [50]
    float* sV  = sC + 50;               // [200]
    float* sTmp= sV + 200;              // [50]
    float* sRed= sTmp + 50;             // [17]
    int*   sIdx= (int*)(sRed + 17);     // [50]

    const int tid = threadIdx.x;
    const int lane = tid & 31, wid = tid >> 5;
    const int row = blockIdx.x;

    if (tid < 50) {
        sIdx[tid] = idx[row * N_ + tid];
        sB[tid] = 2.0f / (1.0f + (float)times[row * N_ + tid]);
    }
    for (int i = tid; i < 200 * 128; i += 512) {
        int h = i >> 7, d = i & 127;
        sW[h * SW_STR + d] = Ws_w[i];
    }
    for (int i = tid; i < 50 * 128; i += 512) {
        int n = i >> 7, d = i & 127;
        sE[i] = emb[(size_t)idx[row * N_ + n] * D_ + d];
    }
    __syncthreads();

    // x = embeds @ Ws^T + b : 500 threads, 5(n) x 4(h) microtile
    if (tid < 500) {
        int tn = tid / 50, th = tid - tn * 50;     // tn 0..9, th 0..49
        float acc[5][4];
#pragma unroll
        for (int i = 0; i < 5; i++)
#pragma unroll
            for (int j = 0; j < 4; j++) acc[i][j] = 0.f;
#pragma unroll 4
        for (int d = 0; d < 128; d++) {
            float a[5], bv[4];
#pragma unroll
            for (int i = 0; i < 5; i++) a[i] = sE[(tn * 5 + i) * 128 + d];
#pragma unroll
            for (int j = 0; j < 4; j++) bv[j] = sW[(th + 50 * j) * SW_STR + d];
#pragma unroll
            for (int i = 0; i < 5; i++)
#pragma unroll
                for (int j = 0; j < 4; j++) acc[i][j] = fmaf(a[i], bv[j], acc[i][j]);
        }
#pragma unroll
        for (int j = 0; j < 4; j++) {
            int h = th + 50 * j;
            float bias = Ws_b[h];
#pragma unroll
            for (int i = 0; i < 5; i++)
                sU[(tn * 5 + i) * H_ + h] = acc[i][j] + bias;
        }
    }
    __syncthreads();

    // L2 normalize rows of sU over H (one warp per n-row, 16 warps)
    for (int n = wid; n < 50; n += 16) {
        float ss = 0.f;
        for (int h = lane; h < H_; h += 32) { float v = sU[n * H_ + h]; ss += v * v; }
#pragma unroll
        for (int o = 16; o > 0; o >>= 1) ss += __shfl_xor_sync(0xffffffffu, ss, o);
        float inv = 1.0f / fmaxf(sqrtf(ss), 1e-12f);
        for (int h = lane; h < H_; h += 32) sU[n * H_ + h] *= inv;
    }
    __syncthreads();

    // dynamic routing, 3 iterations
    for (int r = 0; r < 3; r++) {
        if (wid == 0) {
            float v0 = (lane < 50) ? sB[lane] : -1e30f;
            float v1 = (lane + 32 < 50) ? sB[lane + 32] : -1e30f;
            float m = fmaxf(v0, v1);
#pragma unroll
            for (int o = 16; o > 0; o >>= 1) m = fmaxf(m, __shfl_xor_sync(0xffffffffu, m, o));
            float e0 = (lane < 50) ? expf(v0 - m) : 0.f;
            float e1 = (lane + 32 < 50) ? expf(v1 - m) : 0.f;
            float s = e0 + e1;
#pragma unroll
            for (int o = 16; o > 0; o >>= 1) s += __shfl_xor_sync(0xffffffffu, s, o);
            float sc = 50.0f / s;
            if (lane < 50) sC[lane] = e0 * sc;
            if (lane + 32 < 50) sC[lane + 32] = e1 * sc;
        }
        __syncthreads();
        float mysq = 0.f;
        if (tid < H_) {
            float sv = 0.f;
#pragma unroll 5
            for (int n = 0; n < 50; n++) sv += sC[n] * sU[n * H_ + tid];
            sV[tid] = sv;
            mysq = sv * sv;
        }
#pragma unroll
        for (int o = 16; o > 0; o >>= 1) mysq += __shfl_xor_sync(0xffffffffu, mysq, o);
        if (lane == 0) sRed[wid] = mysq;
        __syncthreads();
        if (tid == 0) {
            float sq = 0.f;
#pragma unroll
            for (int i = 0; i < 16; i++) sq += sRed[i];
            sRed[16] = sq / ((1.0f + sq) * sqrtf(sq + 1e-9f));
        }
        __syncthreads();
        if (tid < H_) sV[tid] *= sRed[16];
        __syncthreads();
        if (r < 2) {
            for (int n = wid; n < 50; n += 16) {
                float dot = 0.f;
                for (int h = lane; h < H_; h += 32) dot += sU[n * H_ + h] * sV[h];
#pragma unroll
                for (int o = 16; o > 0; o >>= 1) dot += __shfl_xor_sync(0xffffffffu, dot, o);
                if (lane == 0) sB[n] += dot;
            }
            __syncthreads();
        }
    }

    // outputs: poses (bf16 padded + fp32) + sparse-p preparation
    if (tid < H_) {
        float v = sV[tid];
        g_v[row * H_ + tid] = v;
        g_vb[row * KPAD + tid] = __float2bfloat16(v);
    } else if (tid < KPAD) {
        g_vb[row * KPAD + tid] = __float2bfloat16(0.f);
    }

    if (tid < 50) {
        int my = sIdx[tid];
        bool first = true;
        float cs = 0.f;
        for (int m = 0; m < 50; m++) {
            if (sIdx[m] == my) {
                cs += sC[m];
                if (m < tid) first = false;
            }
        }
        sTmp[tid] = first ? cs : -1.0f;   // valid sums are > 0
    }
    __syncthreads();
    if (tid == 0) {
        float mp = -1e30f; int K = 0;
        for (int n = 0; n < 50; n++)
            if (sTmp[n] >= 0.f) { K++; mp = fmaxf(mp, sTmp[n]); }
        float Zp = (float)(E_ - K) * expf(-mp);
        for (int n = 0; n < 50; n++)
            if (sTmp[n] >= 0.f) Zp += expf(sTmp[n] - mp);
        int slot = 0;
        for (int n = 0; n < 50; n++)
            if (sTmp[n] >= 0.f) {
                g_fix_id[row * N_ + slot] = sIdx[n];
                g_fix_p[row * N_ + slot] = 0.5f * expf(sTmp[n] - mp) / Zp;
                slot++;
            }
        g_fix_cnt[row] = K;
        g_pbase[row] = 0.5f * expf(-mp) / Zp;
    }
}

// ---------------- K2: bf16 mma GEMM, 128x128 tile, 512 threads ----------------
// PASS2=false: accumulate deterministic exp partials into g_part (no stores).
// PASS2=true : recompute scores and write final log(pb + iz*exp(s)) to out.
__device__ __forceinline__ void mma16816(float* c, const unsigned* a, const unsigned* b) {
    asm volatile("mma.sync.aligned.m16n8k16.row.col.f32.bf16.bf16.f32 "
        "{%0,%1,%2,%3}, {%4,%5,%6,%7}, {%8,%9}, {%0,%1,%2,%3};"
        : "+f"(c[0]), "+f"(c[1]), "+f"(c[2]), "+f"(c[3])
        : "r"(a[0]), "r"(a[1]), "r"(a[2]), "r"(a[3]), "r"(b[0]), "r"(b[1]));
}

template<bool PASS2>
__global__ void __launch_bounds__(512) k_gemm(const float* __restrict__ mlp_b,
                                              float* __restrict__ out)
{
    extern __shared__ __align__(16) char gsm[];
    __nv_bfloat16* sA  = (__nv_bfloat16*)gsm;     // [128][SAS]
    __nv_bfloat16* sBm = sA + GBM * SAS;          // [128][SAS]
    __shared__ float s_part[GBM][16];
    __shared__ float sBias[GBN];

    const int tid = threadIdx.x;
    const int eBase = blockIdx.x * GBN;
    const int rBase = blockIdx.y * GBM;

    if (tid < GBN) {
        int e = eBase + tid;
        sBias[tid] = (e < E_) ? mlp_b[e] : 0.f;
    }
    const uint2* gv = (const uint2*)g_vb;          // 52 uint2 per row
    for (int i = tid; i < GBM * 52; i += 512) {
        int r = i / 52, c = i - r * 52;
        ((uint2*)(sA + r * SAS))[c] = gv[(size_t)(rBase + r) * 52 + c];
    }
    const uint2* gw = (const uint2*)g_wb;
    for (int i = tid; i < GBN * 52; i += 512) {
        int r = i / 52, c = i - r * 52;
        int e = eBase + r;
        uint2 z; z.x = 0u; z.y = 0u;
        ((uint2*)(sBm + r * SAS))[c] = (e < E_) ? gw[(size_t)e * 52 + c] : z;
    }
    __syncthreads();

    const int lane = tid & 31, warp = tid >> 5;
    const int gid = lane >> 2, tig = lane & 3;
    const int wm = warp & 3, wn = warp >> 2;       // 4(m) x 4(n) warps, each 32x32

    float acc[2][4][4];
#pragma unroll
    for (int mi = 0; mi < 2; mi++)
#pragma unroll
        for (int ni = 0; ni < 4; ni++)
#pragma unroll
            for (int q = 0; q < 4; q++) acc[mi][ni][q] = 0.f;

#pragma unroll
    for (int ks = 0; ks < 13; ks++) {
        const int k0 = ks * 16;
        unsigned a[2][4], bf[4][2];
#pragma unroll
        for (int mi = 0; mi < 2; mi++) {
            const __nv_bfloat16* base = sA + (wm * 32 + mi * 16 + gid) * SAS + k0 + 2 * tig;
            a[mi][0] = *(const unsigned*)base;
            a[mi][1] = *(const unsigned*)(base + 8 * SAS);
            a[mi][2] = *(const unsigned*)(base + 8);
            a[mi][3] = *(const unsigned*)(base + 8 * SAS + 8);
        }
#pragma unroll
        for (int ni = 0; ni < 4; ni++) {
            const __nv_bfloat16* base = sBm + (wn * 32 + ni * 8 + gid) * SAS + k0 + 2 * tig;
            bf[ni][0] = *(const unsigned*)base;
            bf[ni][1] = *(const unsigned*)(base + 8);
        }
#pragma unroll
        for (int mi = 0; mi < 2; mi++)
#pragma unroll
            for (int ni = 0; ni < 4; ni++)
                mma16816(acc[mi][ni], a[mi], bf[ni]);
    }

    if (!PASS2) {
        // fixed-order exp partials
        float rs[2][2] = {{0.f, 0.f}, {0.f, 0.f}};
#pragma unroll
        for (int mi = 0; mi < 2; mi++) {
#pragma unroll
            for (int ni = 0; ni < 4; ni++) {
                int ec = wn * 32 + ni * 8 + 2 * tig;
                if (eBase + ec < E_) {
                    float b0 = sBias[ec], b1 = sBias[ec + 1];
                    rs[mi][0] += __expf(acc[mi][ni][0] + b0) + __expf(acc[mi][ni][1] + b1);
                    rs[mi][1] += __expf(acc[mi][ni][2] + b0) + __expf(acc[mi][ni][3] + b1);
                }
            }
        }
        const int slot = wn * 4 + tig;
#pragma unroll
        for (int mi = 0; mi < 2; mi++) {
            s_part[wm * 32 + mi * 16 + gid][slot]     = rs[mi][0];
            s_part[wm * 32 + mi * 16 + gid + 8][slot] = rs[mi][1];
        }
        __syncthreads();
        if (tid < GBM) {
            float s = 0.f;
#pragma unroll
            for (int j = 0; j < 16; j++) s += s_part[tid][j];
            g_part[(size_t)(rBase + tid) * NPART + blockIdx.x] = s;
        }
    } else {
        // final values, coalesced float2 stores
#pragma unroll
        for (int mi = 0; mi < 2; mi++) {
            int r0 = rBase + wm * 32 + mi * 16 + gid;
            float pb0 = g_pbase[r0],     iz0 = g_invZs[r0];
            float pb1 = g_pbase[r0 + 8], iz1 = g_invZs[r0 + 8];
#pragma unroll
            for (int ni = 0; ni < 4; ni++) {
                int ec = wn * 32 + ni * 8 + 2 * tig;
                int e0 = eBase + ec;
                if (e0 < E_) {
                    float b0 = sBias[ec], b1 = sBias[ec + 1];
                    float2 o0, o1;
                    o0.x = __logf(pb0 + iz0 * __expf(acc[mi][ni][0] + b0));
                    o0.y = __logf(pb0 + iz0 * __expf(acc[mi][ni][1] + b1));
                    o1.x = __logf(pb1 + iz1 * __expf(acc[mi][ni][2] + b0));
                    o1.y = __logf(pb1 + iz1 * __expf(acc[mi][ni][3] + b1));
                    *(float2*)(out + (size_t)r0 * E_ + e0)       = o0;
                    *(float2*)(out + (size_t)(r0 + 8) * E_ + e0) = o1;
                }
            }
        }
    }
}

// ---------------- K3: reduce partials -> 0.5/Z_s (warp per row, deterministic) ----------------
__global__ void __launch_bounds__(256) k_reduce() {
    const int warp = threadIdx.x >> 5, lane = threadIdx.x & 31;
    const int row = blockIdx.x * 8 + warp;
    float s = 0.f;
    for (int p = lane; p < NPART; p += 32) s += g_part[(size_t)row * NPART + p];
#pragma unroll
    for (int o = 16; o > 0; o >>= 1) s += __shfl_xor_sync(0xffffffffu, s, o);
    if (lane == 0) g_invZs[row] = 0.5f / s;
}

// ---------------- K4: fixup values at history ids (fp32 dot) ----------------
__global__ void __launch_bounds__(256) k_fixdot(const float* __restrict__ mlp_w,
                                                const float* __restrict__ mlp_b) {
    const int row = blockIdx.x;
    const int warp = threadIdx.x >> 5, lane = threadIdx.x & 31;
    const int cnt = g_fix_cnt[row];
    for (int slot = warp; slot < cnt; slot += 8) {
        int id = g_fix_id[row * N_ + slot];
        float dot = 0.f;
        for (int h = lane; h < H_; h += 32)
            dot += g_v[row * H_ + h] * mlp_w[(size_t)id * H_ + h];
#pragma unroll
        for (int o = 16; o > 0; o >>= 1) dot += __shfl_xor_sync(0xffffffffu, dot, o);
        if (lane == 0) {
            float s = dot + mlp_b[id];
            g_fix_p[row * N_ + slot] =
                __logf(g_fix_p[row * N_ + slot] + g_invZs[row] * __expf(s));
        }
    }
}

// ---------------- K5: write fixed values ----------------
__global__ void k_fix_post(float* __restrict__ out) {
    const int row = blockIdx.x, t = threadIdx.x;
    if (t < g_fix_cnt[row]) {
        int id = g_fix_id[row * N_ + t];
        out[(size_t)row * E_ + id] = g_fix_p[row * N_ + t];
    }
}

// ---------------- launch ----------------
extern "C" void kernel_launch(void* const* d_in, const int* in_sizes, int n_in,
                              void* d_out, int out_size) {
    const int*   idx   = (const int*)d_in[0];
    const int*   times = (const int*)d_in[1];
    const float* emb   = (const float*)d_in[2];
    const float* Ws_w  = (const float*)d_in[3];
    const float* Ws_b  = (const float*)d_in[4];
    const float* mlp_w = (const float*)d_in[5];
    const float* mlp_b = (const float*)d_in[6];
    float* out = (float*)d_out;

    const int gemm_smem = (GBM + GBN) * SAS * 2;   // 110,592 B
    static bool attr_done = false;
    if (!attr_done) {
        cudaFuncSetAttribute(k_routing, cudaFuncAttributeMaxDynamicSharedMemorySize, ROUT_SMEM);
        cudaFuncSetAttribute(k_gemm<false>, cudaFuncAttributeMaxDynamicSharedMemorySize, gemm_smem);
        cudaFuncSetAttribute(k_gemm<true>,  cudaFuncAttributeMaxDynamicSharedMemorySize, gemm_smem);
        attr_done = true;
    }

    k_convert<<<(E_ * 52 + 255) / 256, 256>>>(mlp_w);
    k_routing<<<B_, 512, ROUT_SMEM>>>(idx, times, emb, Ws_w, Ws_b);
    dim3 gg(NPART, B_ / GBM);
    k_gemm<false><<<gg, 512, gemm_smem>>>(mlp_b, out);
    k_reduce<<<B_ / 8, 256>>>();
    k_fixdot<<<B_, 256>>>(mlp_w, mlp_b);
    k_gemm<true><<<gg, 512, gemm_smem>>>(mlp_b, out);
    k_fix_post<<<B_, 64>>>(out);
}

// round 5
// speedup vs baseline: 1.1155x; 1.1155x over previous
#include <cuda_runtime.h>
#include <cuda_bf16.h>
#include <cstdint>

#define B_   512
#define N_   50
#define D_   128
#define H_   200
#define E_   50000
#define KPAD 208            // H_ padded to 13*16 for mma
#define KU   (KPAD/2)       // 104 uints per row
#define GBM  128
#define GBN  128
#define NPART 391           // ceil(E_/GBN)
#define SAS  216            // padded bf16 smem stride (432 B; ldmatrix conflict-free)

// ---------------- static device scratch ----------------
__device__ __nv_bfloat16 g_wb[(size_t)E_ * KPAD]; // mlp_w bf16, K-padded
__device__ __nv_bfloat16 g_vb[B_ * KPAD];         // poses bf16, K-padded
__device__ float g_v[B_ * H_];                    // poses fp32 (for fixdot)
__device__ float g_part[(size_t)B_ * NPART];      // per-(row, e-block) partial sum(exp)
__device__ float g_invZs[B_];                     // 0.5 / Z_s
__device__ float g_pbase[B_];                     // 0.5 * exp(-m_p) / Z_p
__device__ float g_fix_p[B_ * N_];
__device__ int   g_fix_id[B_ * N_];
__device__ int   g_fix_cnt[B_];

// ---------------- K0a/K0b: mlp_w fp32 -> bf16 padded (split for ncu capture alignment) ----------------
__global__ void k_convert(const float* __restrict__ w, int eOff, int eCnt) {
    int i = blockIdx.x * 256 + threadIdx.x;        // uint2 (4 bf16) index within this half
    if (i >= eCnt * 52) return;
    int e = eOff + i / 52, q = i % 52;
    uint2 val;
    if (q < 50) {
        float4 f = *(const float4*)(w + (size_t)e * H_ + 4 * q);
        __nv_bfloat162 lo = __floats2bfloat162_rn(f.x, f.y);
        __nv_bfloat162 hi = __floats2bfloat162_rn(f.z, f.w);
        val.x = *(unsigned*)&lo;
        val.y = *(unsigned*)&hi;
    } else {
        val.x = 0u; val.y = 0u;
    }
    ((uint2*)g_wb)[(size_t)e * 52 + q] = val;
}

// ---------------- K1: gather + projection + routing (one block/row, 512 thr) ----------------
#define SW_STR 129
#define ROUT_SMEM ((200 * SW_STR + 50 * 128 + 50 * 200 + 50 + 50 + 200 + 50 + 17 + 50) * 4)

__global__ void __launch_bounds__(512) k_routing(
    const int* __restrict__ idx, const int* __restrict__ times,
    const float* __restrict__ emb, const float* __restrict__ Ws_w,
    const float* __restrict__ Ws_b)
{
    extern __shared__ float sm[];
    float* sW  = sm;                    // [200][129]
    float* sE  = sW + 200 * SW_STR;     // [50][128]
    float* sU  = sE + 50 * 128;         // [50][200]
    float* sB  = sU + 50 * 200;         // [50]
    float* sC  = sB + 50;               // [50]
    float* sV  = sC + 50;               // [200]
    float* sTmp= sV + 200;              // [50]
    float* sRed= sTmp + 50;             // [17]
    int*   sIdx= (int*)(sRed + 17);     // [50]

    const int tid = threadIdx.x;
    const int lane = tid & 31, wid = tid >> 5;
    const int row = blockIdx.x;

    if (tid < 50) {
        sIdx[tid] = idx[row * N_ + tid];
        sB[tid] = 2.0f / (1.0f + (float)times[row * N_ + tid]);
    }
    for (int i = tid; i < 200 * 128; i += 512) {
        int h = i >> 7, d = i & 127;
        sW[h * SW_STR + d] = Ws_w[i];
    }
    for (int i = tid; i < 50 * 128; i += 512) {
        int n = i >> 7, d = i & 127;
        sE[i] = emb[(size_t)idx[row * N_ + n] * D_ + d];
    }
    __syncthreads();

    if (tid < 500) {
        int tn = tid / 50, th = tid - tn * 50;
        float acc[5][4];
#pragma unroll
        for (int i = 0; i < 5; i++)
#pragma unroll
            for (int j = 0; j < 4; j++) acc[i][j] = 0.f;
#pragma unroll 4
        for (int d = 0; d < 128; d++) {
            float a[5], bv[4];
#pragma unroll
            for (int i = 0; i < 5; i++) a[i] = sE[(tn * 5 + i) * 128 + d];
#pragma unroll
            for (int j = 0; j < 4; j++) bv[j] = sW[(th + 50 * j) * SW_STR + d];
#pragma unroll
            for (int i = 0; i < 5; i++)
#pragma unroll
                for (int j = 0; j < 4; j++) acc[i][j] = fmaf(a[i], bv[j], acc[i][j]);
        }
#pragma unroll
        for (int j = 0; j < 4; j++) {
            int h = th + 50 * j;
            float bias = Ws_b[h];
#pragma unroll
            for (int i = 0; i < 5; i++)
                sU[(tn * 5 + i) * H_ + h] = acc[i][j] + bias;
        }
    }
    __syncthreads();

    for (int n = wid; n < 50; n += 16) {
        float ss = 0.f;
        for (int h = lane; h < H_; h += 32) { float v = sU[n * H_ + h]; ss += v * v; }
#pragma unroll
        for (int o = 16; o > 0; o >>= 1) ss += __shfl_xor_sync(0xffffffffu, ss, o);
        float inv = 1.0f / fmaxf(sqrtf(ss), 1e-12f);
        for (int h = lane; h < H_; h += 32) sU[n * H_ + h] *= inv;
    }
    __syncthreads();

    for (int r = 0; r < 3; r++) {
        if (wid == 0) {
            float v0 = (lane < 50) ? sB[lane] : -1e30f;
            float v1 = (lane + 32 < 50) ? sB[lane + 32] : -1e30f;
            float m = fmaxf(v0, v1);
#pragma unroll
            for (int o = 16; o > 0; o >>= 1) m = fmaxf(m, __shfl_xor_sync(0xffffffffu, m, o));
            float e0 = (lane < 50) ? expf(v0 - m) : 0.f;
            float e1 = (lane + 32 < 50) ? expf(v1 - m) : 0.f;
            float s = e0 + e1;
#pragma unroll
            for (int o = 16; o > 0; o >>= 1) s += __shfl_xor_sync(0xffffffffu, s, o);
            float sc = 50.0f / s;
            if (lane < 50) sC[lane] = e0 * sc;
            if (lane + 32 < 50) sC[lane + 32] = e1 * sc;
        }
        __syncthreads();
        float mysq = 0.f;
        if (tid < H_) {
            float sv = 0.f;
#pragma unroll 5
            for (int n = 0; n < 50; n++) sv += sC[n] * sU[n * H_ + tid];
            sV[tid] = sv;
            mysq = sv * sv;
        }
#pragma unroll
        for (int o = 16; o > 0; o >>= 1) mysq += __shfl_xor_sync(0xffffffffu, mysq, o);
        if (lane == 0) sRed[wid] = mysq;
        __syncthreads();
        if (tid == 0) {
            float sq = 0.f;
#pragma unroll
            for (int i = 0; i < 16; i++) sq += sRed[i];
            sRed[16] = sq / ((1.0f + sq) * sqrtf(sq + 1e-9f));
        }
        __syncthreads();
        if (tid < H_) sV[tid] *= sRed[16];
        __syncthreads();
        if (r < 2) {
            for (int n = wid; n < 50; n += 16) {
                float dot = 0.f;
                for (int h = lane; h < H_; h += 32) dot += sU[n * H_ + h] * sV[h];
#pragma unroll
                for (int o = 16; o > 0; o >>= 1) dot += __shfl_xor_sync(0xffffffffu, dot, o);
                if (lane == 0) sB[n] += dot;
            }
            __syncthreads();
        }
    }

    if (tid < H_) {
        float v = sV[tid];
        g_v[row * H_ + tid] = v;
        g_vb[row * KPAD + tid] = __float2bfloat16(v);
    } else if (tid < KPAD) {
        g_vb[row * KPAD + tid] = __float2bfloat16(0.f);
    }

    if (tid < 50) {
        int my = sIdx[tid];
        bool first = true;
        float cs = 0.f;
        for (int m = 0; m < 50; m++) {
            if (sIdx[m] == my) {
                cs += sC[m];
                if (m < tid) first = false;
            }
        }
        sTmp[tid] = first ? cs : -1.0f;
    }
    __syncthreads();
    if (tid == 0) {
        float mp = -1e30f; int K = 0;
        for (int n = 0; n < 50; n++)
            if (sTmp[n] >= 0.f) { K++; mp = fmaxf(mp, sTmp[n]); }
        float Zp = (float)(E_ - K) * expf(-mp);
        for (int n = 0; n < 50; n++)
            if (sTmp[n] >= 0.f) Zp += expf(sTmp[n] - mp);
        int slot = 0;
        for (int n = 0; n < 50; n++)
            if (sTmp[n] >= 0.f) {
                g_fix_id[row * N_ + slot] = sIdx[n];
                g_fix_p[row * N_ + slot] = 0.5f * expf(sTmp[n] - mp) / Zp;
                slot++;
            }
        g_fix_cnt[row] = K;
        g_pbase[row] = 0.5f * expf(-mp) / Zp;
    }
}

// ---------------- K2: bf16 mma GEMM, 128x128 tile, 512 thr, ldmatrix frags ----------------
__device__ __forceinline__ uint32_t smem_u32(const void* p) {
    uint32_t a;
    asm("{ .reg .u64 t; cvta.to.shared.u64 t, %1; cvt.u32.u64 %0, t; }" : "=r"(a) : "l"(p));
    return a;
}
__device__ __forceinline__ void mma16816(float* c, const unsigned* a, const unsigned* b) {
    asm volatile("mma.sync.aligned.m16n8k16.row.col.f32.bf16.bf16.f32 "
        "{%0,%1,%2,%3}, {%4,%5,%6,%7}, {%8,%9}, {%0,%1,%2,%3};"
        : "+f"(c[0]), "+f"(c[1]), "+f"(c[2]), "+f"(c[3])
        : "r"(a[0]), "r"(a[1]), "r"(a[2]), "r"(a[3]), "r"(b[0]), "r"(b[1]));
}
__device__ __forceinline__ void ldsm_x4(unsigned* r, uint32_t addr) {
    asm volatile("ldmatrix.sync.aligned.m8n8.x4.shared.b16 {%0,%1,%2,%3}, [%4];"
        : "=r"(r[0]), "=r"(r[1]), "=r"(r[2]), "=r"(r[3]) : "r"(addr));
}

#define GEMM_DSMEM ((GBM + GBN) * SAS * 2 + 512)

template<bool PASS2>
__global__ void __launch_bounds__(512) k_gemm(const float* __restrict__ mlp_b,
                                              float* __restrict__ out)
{
    extern __shared__ __align__(16) char gsm[];
    __nv_bfloat16* sA   = (__nv_bfloat16*)gsm;    // [128][SAS] batch rows
    __nv_bfloat16* sBm  = sA + GBM * SAS;         // [128][SAS] entities
    float*         sBias= (float*)(sBm + GBN * SAS); // [128]
    float (*s_part)[16] = (float (*)[16])gsm;     // alias over sA after mainloop

    const int tid = threadIdx.x;
    const int eBase = blockIdx.x * GBN;
    const int rBase = blockIdx.y * GBM;

    if (tid < GBN) {
        int e = eBase + tid;
        sBias[tid] = (e < E_) ? mlp_b[e] : 0.f;
    }
    const uint2* gv = (const uint2*)g_vb;
    for (int i = tid; i < GBM * 52; i += 512) {
        int r = i / 52, c = i - r * 52;
        ((uint2*)(sA + r * SAS))[c] = gv[(size_t)(rBase + r) * 52 + c];
    }
    const uint2* gw = (const uint2*)g_wb;
    for (int i = tid; i < GBN * 52; i += 512) {
        int r = i / 52, c = i - r * 52;
        int e = eBase + r;
        uint2 z; z.x = 0u; z.y = 0u;
        ((uint2*)(sBm + r * SAS))[c] = (e < E_) ? gw[(size_t)e * 52 + c] : z;
    }
    __syncthreads();

    const int lane = tid & 31, warp = tid >> 5;
    const int gid = lane >> 2, tig = lane & 3;
    const int wm = warp & 3, wn = warp >> 2;       // 4(m) x 4(n) warps, each 32x32

    // ldmatrix source addresses (bytes)
    const uint32_t sA_u = smem_u32(sA), sB_u = smem_u32(sBm);
    uint32_t aAddr0 = sA_u + (uint32_t)(((wm * 32 + (lane & 15)) * SAS + ((lane >> 4) * 8)) * 2);
    uint32_t aAddr1 = aAddr0 + 16u * SAS * 2u;
    uint32_t bAddr0 = sB_u + (uint32_t)(((wn * 32 + (lane & 7) + (((lane >> 4) & 1) * 8)) * SAS
                                        + (((lane >> 3) & 1) * 8)) * 2);
    uint32_t bAddr1 = bAddr0 + 16u * SAS * 2u;

    float acc[2][4][4];
#pragma unroll
    for (int mi = 0; mi < 2; mi++)
#pragma unroll
        for (int ni = 0; ni < 4; ni++)
#pragma unroll
            for (int q = 0; q < 4; q++) acc[mi][ni][q] = 0.f;

#pragma unroll
    for (int ks = 0; ks < 13; ks++) {
        const uint32_t koff = ks * 32u;            // 16 bf16 = 32 B
        unsigned a0[4], a1[4], b0[4], b1[4];
        ldsm_x4(a0, aAddr0 + koff);
        ldsm_x4(a1, aAddr1 + koff);
        ldsm_x4(b0, bAddr0 + koff);                // ni 0 (regs 0,1), ni 1 (regs 2,3)
        ldsm_x4(b1, bAddr1 + koff);                // ni 2, ni 3
        mma16816(acc[0][0], a0, b0 + 0);
        mma16816(acc[0][1], a0, b0 + 2);
        mma16816(acc[0][2], a0, b1 + 0);
        mma16816(acc[0][3], a0, b1 + 2);
        mma16816(acc[1][0], a1, b0 + 0);
        mma16816(acc[1][1], a1, b0 + 2);
        mma16816(acc[1][2], a1, b1 + 0);
        mma16816(acc[1][3], a1, b1 + 2);
    }

    if (!PASS2) {
        // fixed-order exp partials; s_part aliases sA, so barrier first
        float rs[2][2] = {{0.f, 0.f}, {0.f, 0.f}};
        float bv[4][2];
#pragma unroll
        for (int ni = 0; ni < 4; ni++) {
            int ec = wn * 32 + ni * 8 + 2 * tig;
            bv[ni][0] = sBias[ec];
            bv[ni][1] = sBias[ec + 1];
        }
        const bool ev = true;  // guard folded below per-ni
#pragma unroll
        for (int mi = 0; mi < 2; mi++) {
#pragma unroll
            for (int ni = 0; ni < 4; ni++) {
                int e0 = eBase + wn * 32 + ni * 8 + 2 * tig;
                if (e0 < E_) {
                    rs[mi][0] += __expf(acc[mi][ni][0] + bv[ni][0]) + __expf(acc[mi][ni][1] + bv[ni][1]);
                    rs[mi][1] += __expf(acc[mi][ni][2] + bv[ni][0]) + __expf(acc[mi][ni][3] + bv[ni][1]);
                }
            }
        }
        (void)ev;
        __syncthreads();   // sA dead -> safe to alias as s_part
        const int slot = wn * 4 + tig;
#pragma unroll
        for (int mi = 0; mi < 2; mi++) {
            s_part[wm * 32 + mi * 16 + gid][slot]     = rs[mi][0];
            s_part[wm * 32 + mi * 16 + gid + 8][slot] = rs[mi][1];
        }
        __syncthreads();
        if (tid < GBM) {
            float s = 0.f;
#pragma unroll
            for (int j = 0; j < 16; j++) s += s_part[tid][j];
            g_part[(size_t)(rBase + tid) * NPART + blockIdx.x] = s;
        }
    } else {
#pragma unroll
        for (int mi = 0; mi < 2; mi++) {
            int r0 = rBase + wm * 32 + mi * 16 + gid;
            float pb0 = g_pbase[r0],     iz0 = g_invZs[r0];
            float pb1 = g_pbase[r0 + 8], iz1 = g_invZs[r0 + 8];
#pragma unroll
            for (int ni = 0; ni < 4; ni++) {
                int ec = wn * 32 + ni * 8 + 2 * tig;
                int e0 = eBase + ec;
                if (e0 < E_) {
                    float b0 = sBias[ec], b1 = sBias[ec + 1];
                    float2 o0, o1;
                    o0.x = __logf(pb0 + iz0 * __expf(acc[mi][ni][0] + b0));
                    o0.y = __logf(pb0 + iz0 * __expf(acc[mi][ni][1] + b1));
                    o1.x = __logf(pb1 + iz1 * __expf(acc[mi][ni][2] + b0));
                    o1.y = __logf(pb1 + iz1 * __expf(acc[mi][ni][3] + b1));
                    *(float2*)(out + (size_t)r0 * E_ + e0)       = o0;
                    *(float2*)(out + (size_t)(r0 + 8) * E_ + e0) = o1;
                }
            }
        }
    }
}

// ---------------- K3: reduce partials -> 0.5/Z_s (block per row, deterministic) ----------------
__global__ void __launch_bounds__(128) k_reduce() {
    __shared__ float red[128];
    const int row = blockIdx.x, tid = threadIdx.x;
    float s = 0.f;
    for (int p = tid; p < NPART; p += 128) s += g_part[(size_t)row * NPART + p];
    red[tid] = s;
    __syncthreads();
    for (int o = 64; o > 0; o >>= 1) {
        if (tid < o) red[tid] += red[tid + o];
        __syncthreads();
    }
    if (tid == 0) g_invZs[row] = 0.5f / red[0];
}

// ---------------- K4: fixup values at history ids (fp32 dot) ----------------
__global__ void __launch_bounds__(256) k_fixdot(const float* __restrict__ mlp_w,
                                                const float* __restrict__ mlp_b) {
    const int row = blockIdx.x;
    const int warp = threadIdx.x >> 5, lane = threadIdx.x & 31;
    const int cnt = g_fix_cnt[row];
    for (int slot = warp; slot < cnt; slot += 8) {
        int id = g_fix_id[row * N_ + slot];
        float dot = 0.f;
        for (int h = lane; h < H_; h += 32)
            dot += g_v[row * H_ + h] * mlp_w[(size_t)id * H_ + h];
#pragma unroll
        for (int o = 16; o > 0; o >>= 1) dot += __shfl_xor_sync(0xffffffffu, dot, o);
        if (lane == 0) {
            float s = dot + mlp_b[id];
            g_fix_p[row * N_ + slot] =
                __logf(g_fix_p[row * N_ + slot] + g_invZs[row] * __expf(s));
        }
    }
}

// ---------------- K5: write fixed values ----------------
__global__ void k_fix_post(float* __restrict__ out) {
    const int row = blockIdx.x, t = threadIdx.x;
    if (t < g_fix_cnt[row]) {
        int id = g_fix_id[row * N_ + t];
        out[(size_t)row * E_ + id] = g_fix_p[row * N_ + t];
    }
}

// ---------------- launch ----------------
extern "C" void kernel_launch(void* const* d_in, const int* in_sizes, int n_in,
                              void* d_out, int out_size) {
    const int*   idx   = (const int*)d_in[0];
    const int*   times = (const int*)d_in[1];
    const float* emb   = (const float*)d_in[2];
    const float* Ws_w  = (const float*)d_in[3];
    const float* Ws_b  = (const float*)d_in[4];
    const float* mlp_w = (const float*)d_in[5];
    const float* mlp_b = (const float*)d_in[6];
    float* out = (float*)d_out;

    static bool attr_done = false;
    if (!attr_done) {
        cudaFuncSetAttribute(k_routing, cudaFuncAttributeMaxDynamicSharedMemorySize, ROUT_SMEM);
        cudaFuncSetAttribute(k_gemm<false>, cudaFuncAttributeMaxDynamicSharedMemorySize, GEMM_DSMEM);
        cudaFuncSetAttribute(k_gemm<true>,  cudaFuncAttributeMaxDynamicSharedMemorySize, GEMM_DSMEM);
        attr_done = true;
    }

    const int eHalf = E_ / 2;   // 25000
    k_convert<<<(eHalf * 52 + 255) / 256, 256>>>(mlp_w, 0, eHalf);
    k_convert<<<(eHalf * 52 + 255) / 256, 256>>>(mlp_w, eHalf, E_ - eHalf);
    k_routing<<<B_, 512, ROUT_SMEM>>>(idx, times, emb, Ws_w, Ws_b);
    dim3 gg(NPART, B_ / GBM);
    k_gemm<false><<<gg, 512, GEMM_DSMEM>>>(mlp_b, out);   // process launch #5 -> ncu capture
    k_reduce<<<B_, 128>>>();
    k_fixdot<<<B_, 256>>>(mlp_w, mlp_b);
    k_gemm<true><<<gg, 512, GEMM_DSMEM>>>(mlp_b, out);
    k_fix_post<<<B_, 64>>>(out);
}

// round 6
// speedup vs baseline: 1.2054x; 1.0806x over previous
#include <cuda_runtime.h>
#include <cuda_bf16.h>
#include <cuda_fp16.h>
#include <cstdint>

#define B_   512
#define N_   50
#define D_   128
#define H_   200
#define E_   50000
#define KPAD 208            // H_ padded to 13*16 for mma
#define KU   (KPAD/2)       // 104 uints per row
#define GBM  128
#define GBN  128
#define NPART 391           // ceil(E_/GBN)
#define SAS  216            // padded bf16 smem stride (ldmatrix conflict-free)

// ---------------- static device scratch ----------------
__device__ __nv_bfloat16 g_wb[(size_t)E_ * KPAD]; // mlp_w bf16, K-padded (20.8 MB)
__device__ __align__(16) __half g_sc[(size_t)B_ * E_]; // fp16 scores (51.2 MB, L2-resident)
__device__ __nv_bfloat16 g_vb[B_ * KPAD];         // poses bf16, K-padded
__device__ float g_v[B_ * H_];                    // poses fp32 (for fixdot)
__device__ float g_part[(size_t)B_ * NPART];      // per-(row, e-block) partial sum(exp)
__device__ float g_invZs[B_];                     // 0.5 / Z_s
__device__ float g_pbase[B_];                     // 0.5 * exp(-m_p) / Z_p
__device__ float g_fix_p[B_ * N_];
__device__ int   g_fix_id[B_ * N_];
__device__ int   g_fix_cnt[B_];

// ---------------- K0 (x3): mlp_w fp32 -> bf16 padded ----------------
__global__ void k_convert(const float* __restrict__ w, int eOff, int eCnt) {
    int i = blockIdx.x * 256 + threadIdx.x;        // uint2 (4 bf16) index within chunk
    if (i >= eCnt * 52) return;
    int e = eOff + i / 52, q = i % 52;
    uint2 val;
    if (q < 50) {
        float4 f = *(const float4*)(w + (size_t)e * H_ + 4 * q);
        __nv_bfloat162 lo = __floats2bfloat162_rn(f.x, f.y);
        __nv_bfloat162 hi = __floats2bfloat162_rn(f.z, f.w);
        val.x = *(unsigned*)&lo;
        val.y = *(unsigned*)&hi;
    } else {
        val.x = 0u; val.y = 0u;
    }
    ((uint2*)g_wb)[(size_t)e * 52 + q] = val;
}

// ---------------- K1: gather + projection + routing (one block/row, 512 thr) ----------------
#define SW_STR 129
#define ROUT_SMEM ((200 * SW_STR + 50 * 128 + 50 * 200 + 50 + 50 + 200 + 50 + 17 + 50) * 4)

__global__ void __launch_bounds__(512) k_routing(
    const int* __restrict__ idx, const int* __restrict__ times,
    const float* __restrict__ emb, const float* __restrict__ Ws_w,
    const float* __restrict__ Ws_b)
{
    extern __shared__ float sm[];
    float* sW  = sm;                    // [200][129]
    float* sE  = sW + 200 * SW_STR;     // [50][128]
    float* sU  = sE + 50 * 128;         // [50][200]
    float* sB  = sU + 50 * 200;         // [50]
    float* sC  = sB + 50;               // [50]
    float* sV  = sC + 50;               // [200]
    float* sTmp= sV + 200;              // [50]
    float* sRed= sTmp + 50;             // [17]
    int*   sIdx= (int*)(sRed + 17);     // [50]

    const int tid = threadIdx.x;
    const int lane = tid & 31, wid = tid >> 5;
    const int row = blockIdx.x;

    if (tid < 50) {
        sIdx[tid] = idx[row * N_ + tid];
        sB[tid] = 2.0f / (1.0f + (float)times[row * N_ + tid]);
    }
    for (int i = tid; i < 200 * 128; i += 512) {
        int h = i >> 7, d = i & 127;
        sW[h * SW_STR + d] = Ws_w[i];
    }
    for (int i = tid; i < 50 * 128; i += 512) {
        int n = i >> 7, d = i & 127;
        sE[i] = emb[(size_t)idx[row * N_ + n] * D_ + d];
    }
    __syncthreads();

    if (tid < 500) {
        int tn = tid / 50, th = tid - tn * 50;
        float acc[5][4];
#pragma unroll
        for (int i = 0; i < 5; i++)
#pragma unroll
            for (int j = 0; j < 4; j++) acc[i][j] = 0.f;
#pragma unroll 4
        for (int d = 0; d < 128; d++) {
            float a[5], bv[4];
#pragma unroll
            for (int i = 0; i < 5; i++) a[i] = sE[(tn * 5 + i) * 128 + d];
#pragma unroll
            for (int j = 0; j < 4; j++) bv[j] = sW[(th + 50 * j) * SW_STR + d];
#pragma unroll
            for (int i = 0; i < 5; i++)
#pragma unroll
                for (int j = 0; j < 4; j++) acc[i][j] = fmaf(a[i], bv[j], acc[i][j]);
        }
#pragma unroll
        for (int j = 0; j < 4; j++) {
            int h = th + 50 * j;
            float bias = Ws_b[h];
#pragma unroll
            for (int i = 0; i < 5; i++)
                sU[(tn * 5 + i) * H_ + h] = acc[i][j] + bias;
        }
    }
    __syncthreads();

    for (int n = wid; n < 50; n += 16) {
        float ss = 0.f;
        for (int h = lane; h < H_; h += 32) { float v = sU[n * H_ + h]; ss += v * v; }
#pragma unroll
        for (int o = 16; o > 0; o >>= 1) ss += __shfl_xor_sync(0xffffffffu, ss, o);
        float inv = 1.0f / fmaxf(sqrtf(ss), 1e-12f);
        for (int h = lane; h < H_; h += 32) sU[n * H_ + h] *= inv;
    }
    __syncthreads();

    for (int r = 0; r < 3; r++) {
        if (wid == 0) {
            float v0 = (lane < 50) ? sB[lane] : -1e30f;
            float v1 = (lane + 32 < 50) ? sB[lane + 32] : -1e30f;
            float m = fmaxf(v0, v1);
#pragma unroll
            for (int o = 16; o > 0; o >>= 1) m = fmaxf(m, __shfl_xor_sync(0xffffffffu, m, o));
            float e0 = (lane < 50) ? expf(v0 - m) : 0.f;
            float e1 = (lane + 32 < 50) ? expf(v1 - m) : 0.f;
            float s = e0 + e1;
#pragma unroll
            for (int o = 16; o > 0; o >>= 1) s += __shfl_xor_sync(0xffffffffu, s, o);
            float sc = 50.0f / s;
            if (lane < 50) sC[lane] = e0 * sc;
            if (lane + 32 < 50) sC[lane + 32] = e1 * sc;
        }
        __syncthreads();
        float mysq = 0.f;
        if (tid < H_) {
            float sv = 0.f;
#pragma unroll 5
            for (int n = 0; n < 50; n++) sv += sC[n] * sU[n * H_ + tid];
            sV[tid] = sv;
            mysq = sv * sv;
        }
#pragma unroll
        for (int o = 16; o > 0; o >>= 1) mysq += __shfl_xor_sync(0xffffffffu, mysq, o);
        if (lane == 0) sRed[wid] = mysq;
        __syncthreads();
        if (tid == 0) {
            float sq = 0.f;
#pragma unroll
            for (int i = 0; i < 16; i++) sq += sRed[i];
            sRed[16] = sq / ((1.0f + sq) * sqrtf(sq + 1e-9f));
        }
        __syncthreads();
        if (tid < H_) sV[tid] *= sRed[16];
        __syncthreads();
        if (r < 2) {
            for (int n = wid; n < 50; n += 16) {
                float dot = 0.f;
                for (int h = lane; h < H_; h += 32) dot += sU[n * H_ + h] * sV[h];
#pragma unroll
                for (int o = 16; o > 0; o >>= 1) dot += __shfl_xor_sync(0xffffffffu, dot, o);
                if (lane == 0) sB[n] += dot;
            }
            __syncthreads();
        }
    }

    if (tid < H_) {
        float v = sV[tid];
        g_v[row * H_ + tid] = v;
        g_vb[row * KPAD + tid] = __float2bfloat16(v);
    } else if (tid < KPAD) {
        g_vb[row * KPAD + tid] = __float2bfloat16(0.f);
    }

    if (tid < 50) {
        int my = sIdx[tid];
        bool first = true;
        float cs = 0.f;
        for (int m = 0; m < 50; m++) {
            if (sIdx[m] == my) {
                cs += sC[m];
                if (m < tid) first = false;
            }
        }
        sTmp[tid] = first ? cs : -1.0f;
    }
    __syncthreads();
    if (tid == 0) {
        float mp = -1e30f; int K = 0;
        for (int n = 0; n < 50; n++)
            if (sTmp[n] >= 0.f) { K++; mp = fmaxf(mp, sTmp[n]); }
        float Zp = (float)(E_ - K) * expf(-mp);
        for (int n = 0; n < 50; n++)
            if (sTmp[n] >= 0.f) Zp += expf(sTmp[n] - mp);
        int slot = 0;
        for (int n = 0; n < 50; n++)
            if (sTmp[n] >= 0.f) {
                g_fix_id[row * N_ + slot] = sIdx[n];
                g_fix_p[row * N_ + slot] = 0.5f * expf(sTmp[n] - mp) / Zp;
                slot++;
            }
        g_fix_cnt[row] = K;
        g_pbase[row] = 0.5f * expf(-mp) / Zp;
    }
}

// ---------------- K2: bf16 mma GEMM (single pass): half scores + exp partials ----------------
__device__ __forceinline__ uint32_t smem_u32(const void* p) {
    uint32_t a;
    asm("{ .reg .u64 t; cvta.to.shared.u64 t, %1; cvt.u32.u64 %0, t; }" : "=r"(a) : "l"(p));
    return a;
}
__device__ __forceinline__ void mma16816(float* c, const unsigned* a, const unsigned* b) {
    asm volatile("mma.sync.aligned.m16n8k16.row.col.f32.bf16.bf16.f32 "
        "{%0,%1,%2,%3}, {%4,%5,%6,%7}, {%8,%9}, {%0,%1,%2,%3};"
        : "+f"(c[0]), "+f"(c[1]), "+f"(c[2]), "+f"(c[3])
        : "r"(a[0]), "r"(a[1]), "r"(a[2]), "r"(a[3]), "r"(b[0]), "r"(b[1]));
}
__device__ __forceinline__ void ldsm_x4(unsigned* r, uint32_t addr) {
    asm volatile("ldmatrix.sync.aligned.m8n8.x4.shared.b16 {%0,%1,%2,%3}, [%4];"
        : "=r"(r[0]), "=r"(r[1]), "=r"(r[2]), "=r"(r[3]) : "r"(addr));
}

#define GEMM_DSMEM ((GBM + GBN) * SAS * 2 + 512)

__global__ void __launch_bounds__(512) k_gemm(const float* __restrict__ mlp_b)
{
    extern __shared__ __align__(16) char gsm[];
    __nv_bfloat16* sA   = (__nv_bfloat16*)gsm;       // [128][SAS] batch rows
    __nv_bfloat16* sBm  = sA + GBM * SAS;            // [128][SAS] entities
    float*         sBias= (float*)(sBm + GBN * SAS); // [128]
    float (*s_part)[16] = (float (*)[16])gsm;        // alias over sA after mainloop

    const int tid = threadIdx.x;
    const int eBase = blockIdx.x * GBN;
    const int rBase = blockIdx.y * GBM;

    if (tid < GBN) {
        int e = eBase + tid;
        sBias[tid] = (e < E_) ? mlp_b[e] : 0.f;
    }
    const uint2* gv = (const uint2*)g_vb;
    for (int i = tid; i < GBM * 52; i += 512) {
        int r = i / 52, c = i - r * 52;
        ((uint2*)(sA + r * SAS))[c] = gv[(size_t)(rBase + r) * 52 + c];
    }
    const uint2* gw = (const uint2*)g_wb;
    for (int i = tid; i < GBN * 52; i += 512) {
        int r = i / 52, c = i - r * 52;
        int e = eBase + r;
        uint2 z; z.x = 0u; z.y = 0u;
        ((uint2*)(sBm + r * SAS))[c] = (e < E_) ? gw[(size_t)e * 52 + c] : z;
    }
    __syncthreads();

    const int lane = tid & 31, warp = tid >> 5;
    const int gid = lane >> 2, tig = lane & 3;
    const int wm = warp & 3, wn = warp >> 2;       // 4(m) x 4(n) warps, each 32x32

    const uint32_t sA_u = smem_u32(sA), sB_u = smem_u32(sBm);
    uint32_t aAddr0 = sA_u + (uint32_t)(((wm * 32 + (lane & 15)) * SAS + ((lane >> 4) * 8)) * 2);
    uint32_t aAddr1 = aAddr0 + 16u * SAS * 2u;
    uint32_t bAddr0 = sB_u + (uint32_t)(((wn * 32 + (lane & 7) + (((lane >> 4) & 1) * 8)) * SAS
                                        + (((lane >> 3) & 1) * 8)) * 2);
    uint32_t bAddr1 = bAddr0 + 16u * SAS * 2u;

    float acc[2][4][4];
#pragma unroll
    for (int mi = 0; mi < 2; mi++)
#pragma unroll
        for (int ni = 0; ni < 4; ni++)
#pragma unroll
            for (int q = 0; q < 4; q++) acc[mi][ni][q] = 0.f;

#pragma unroll
    for (int ks = 0; ks < 13; ks++) {
        const uint32_t koff = ks * 32u;
        unsigned a0[4], a1[4], b0[4], b1[4];
        ldsm_x4(a0, aAddr0 + koff);
        ldsm_x4(a1, aAddr1 + koff);
        ldsm_x4(b0, bAddr0 + koff);
        ldsm_x4(b1, bAddr1 + koff);
        mma16816(acc[0][0], a0, b0 + 0);
        mma16816(acc[0][1], a0, b0 + 2);
        mma16816(acc[0][2], a0, b1 + 0);
        mma16816(acc[0][3], a0, b1 + 2);
        mma16816(acc[1][0], a1, b0 + 0);
        mma16816(acc[1][1], a1, b0 + 2);
        mma16816(acc[1][2], a1, b1 + 0);
        mma16816(acc[1][3], a1, b1 + 2);
    }

    // epilogue: bias, half score store, fixed-order exp partials
    float rs[2][2] = {{0.f, 0.f}, {0.f, 0.f}};
#pragma unroll
    for (int mi = 0; mi < 2; mi++) {
        int r0 = rBase + wm * 32 + mi * 16 + gid;
#pragma unroll
        for (int ni = 0; ni < 4; ni++) {
            int ec = wn * 32 + ni * 8 + 2 * tig;
            int e0 = eBase + ec;
            if (e0 < E_) {
                float b0 = sBias[ec], b1 = sBias[ec + 1];
                float s00 = acc[mi][ni][0] + b0;
                float s01 = acc[mi][ni][1] + b1;
                float s10 = acc[mi][ni][2] + b0;
                float s11 = acc[mi][ni][3] + b1;
                *(__half2*)(g_sc + (size_t)r0 * E_ + e0)       = __floats2half2_rn(s00, s01);
                *(__half2*)(g_sc + (size_t)(r0 + 8) * E_ + e0) = __floats2half2_rn(s10, s11);
                rs[mi][0] += __expf(s00) + __expf(s01);
                rs[mi][1] += __expf(s10) + __expf(s11);
            }
        }
    }
    __syncthreads();   // sA dead -> safe to alias as s_part
    const int slot = wn * 4 + tig;
#pragma unroll
    for (int mi = 0; mi < 2; mi++) {
        s_part[wm * 32 + mi * 16 + gid][slot]     = rs[mi][0];
        s_part[wm * 32 + mi * 16 + gid + 8][slot] = rs[mi][1];
    }
    __syncthreads();
    if (tid < GBM) {
        float s = 0.f;
#pragma unroll
        for (int j = 0; j < 16; j++) s += s_part[tid][j];
        g_part[(size_t)(rBase + tid) * NPART + blockIdx.x] = s;
    }
}

// ---------------- K3: reduce partials -> 0.5/Z_s ----------------
__global__ void __launch_bounds__(128) k_reduce() {
    __shared__ float red[128];
    const int row = blockIdx.x, tid = threadIdx.x;
    float s = 0.f;
    for (int p = tid; p < NPART; p += 128) s += g_part[(size_t)row * NPART + p];
    red[tid] = s;
    __syncthreads();
    for (int o = 64; o > 0; o >>= 1) {
        if (tid < o) red[tid] += red[tid + o];
        __syncthreads();
    }
    if (tid == 0) g_invZs[row] = 0.5f / red[0];
}

// ---------------- K4: fixup values at history ids (fp32 dot) ----------------
__global__ void __launch_bounds__(256) k_fixdot(const float* __restrict__ mlp_w,
                                                const float* __restrict__ mlp_b) {
    const int row = blockIdx.x;
    const int warp = threadIdx.x >> 5, lane = threadIdx.x & 31;
    const int cnt = g_fix_cnt[row];
    for (int slot = warp; slot < cnt; slot += 8) {
        int id = g_fix_id[row * N_ + slot];
        float dot = 0.f;
        for (int h = lane; h < H_; h += 32)
            dot += g_v[row * H_ + h] * mlp_w[(size_t)id * H_ + h];
#pragma unroll
        for (int o = 16; o > 0; o >>= 1) dot += __shfl_xor_sync(0xffffffffu, dot, o);
        if (lane == 0) {
            float s = dot + mlp_b[id];
            g_fix_p[row * N_ + slot] =
                __logf(g_fix_p[row * N_ + slot] + g_invZs[row] * __expf(s));
        }
    }
}

// ---------------- K5: finalize from half scores ----------------
__global__ void __launch_bounds__(256) k_finalize(float* __restrict__ out) {
    const int row = blockIdx.y;
    const int q = blockIdx.x * 256 + threadIdx.x;   // group of 4 elements
    if (q >= E_ / 4) return;
    uint2 packed = *(const uint2*)(g_sc + (size_t)row * E_ + 4 * q);
    __half2 h0 = *(__half2*)&packed.x;
    __half2 h1 = *(__half2*)&packed.y;
    float2 f0 = __half22float2(h0);
    float2 f1 = __half22float2(h1);
    const float pb = g_pbase[row], iz = g_invZs[row];
    float4 v;
    v.x = __logf(pb + iz * __expf(f0.x));
    v.y = __logf(pb + iz * __expf(f0.y));
    v.z = __logf(pb + iz * __expf(f1.x));
    v.w = __logf(pb + iz * __expf(f1.y));
    *(float4*)(out + (size_t)row * E_ + 4 * q) = v;
}

// ---------------- K6: write fixed values for history ids ----------------
__global__ void k_fix_post(float* __restrict__ out) {
    const int row = blockIdx.x, t = threadIdx.x;
    if (t < g_fix_cnt[row]) {
        int id = g_fix_id[row * N_ + t];
        out[(size_t)row * E_ + id] = g_fix_p[row * N_ + t];
    }
}

// ---------------- launch ----------------
extern "C" void kernel_launch(void* const* d_in, const int* in_sizes, int n_in,
                              void* d_out, int out_size) {
    const int*   idx   = (const int*)d_in[0];
    const int*   times = (const int*)d_in[1];
    const float* emb   = (const float*)d_in[2];
    const float* Ws_w  = (const float*)d_in[3];
    const float* Ws_b  = (const float*)d_in[4];
    const float* mlp_w = (const float*)d_in[5];
    const float* mlp_b = (const float*)d_in[6];
    float* out = (float*)d_out;

    static bool attr_done = false;
    if (!attr_done) {
        cudaFuncSetAttribute(k_routing, cudaFuncAttributeMaxDynamicSharedMemorySize, ROUT_SMEM);
        cudaFuncSetAttribute(k_gemm,    cudaFuncAttributeMaxDynamicSharedMemorySize, GEMM_DSMEM);
        attr_done = true;
    }

    // convert split 3-way so process-launch capture (-s 5) lands on k_routing
    const int c1 = 16668, c2 = 16668, c3 = E_ - c1 - c2;
    k_convert<<<(c1 * 52 + 255) / 256, 256>>>(mlp_w, 0, c1);
    k_convert<<<(c2 * 52 + 255) / 256, 256>>>(mlp_w, c1, c2);
    k_convert<<<(c3 * 52 + 255) / 256, 256>>>(mlp_w, c1 + c2, c3);
    k_routing<<<B_, 512, ROUT_SMEM>>>(idx, times, emb, Ws_w, Ws_b);
    dim3 gg(NPART, B_ / GBM);
    k_gemm<<<gg, 512, GEMM_DSMEM>>>(mlp_b);
    k_reduce<<<B_, 128>>>();
    k_fixdot<<<B_, 256>>>(mlp_w, mlp_b);
    dim3 gf((E_ / 4 + 255) / 256, B_);
    k_finalize<<<gf, 256>>>(out);
    k_fix_post<<<B_, 64>>>(out);
}

// round 7
// speedup vs baseline: 1.6069x; 1.3331x over previous
#include <cuda_runtime.h>
#include <cuda_bf16.h>
#include <cuda_fp16.h>
#include <cstdint>

#define B_   512
#define N_   50
#define D_   128
#define H_   200
#define E_   50000
#define KPAD 208            // H_ padded to 13*16 for decoder mma
#define GBM  128
#define GBN  128
#define NPART 391           // ceil(E_/GBN)
#define SAS  216            // decoder gemm smem stride
#define PSTR 136            // projection gemm smem stride (bf16)

// ---------------- static device scratch ----------------
__device__ __nv_bfloat16 g_wb[(size_t)E_ * KPAD];      // mlp_w bf16, K-padded (20.8 MB)
__device__ __align__(16) __half g_sc[(size_t)B_ * E_]; // fp16 scores (51.2 MB)
__device__ __align__(16) float g_x[(size_t)B_ * N_ * H_]; // projected x (20.5 MB)
__device__ __nv_bfloat16 g_vb[B_ * KPAD];              // poses bf16, K-padded
__device__ float g_v[B_ * H_];                         // poses fp32 (for fixdot)
__device__ float g_part[(size_t)B_ * NPART];           // per-(row, e-block) exp partials
__device__ float g_invZs[B_];                          // 0.5 / Z_s
__device__ float g_pbase[B_];                          // 0.5 * exp(-m_p) / Z_p
__device__ float g_fix_p[B_ * N_];
__device__ int   g_fix_id[B_ * N_];
__device__ int   g_fix_cnt[B_];

// ---------------- shared PTX helpers ----------------
__device__ __forceinline__ uint32_t smem_u32(const void* p) {
    uint32_t a;
    asm("{ .reg .u64 t; cvta.to.shared.u64 t, %1; cvt.u32.u64 %0, t; }" : "=r"(a) : "l"(p));
    return a;
}
__device__ __forceinline__ void mma16816(float* c, const unsigned* a, const unsigned* b) {
    asm volatile("mma.sync.aligned.m16n8k16.row.col.f32.bf16.bf16.f32 "
        "{%0,%1,%2,%3}, {%4,%5,%6,%7}, {%8,%9}, {%0,%1,%2,%3};"
        : "+f"(c[0]), "+f"(c[1]), "+f"(c[2]), "+f"(c[3])
        : "r"(a[0]), "r"(a[1]), "r"(a[2]), "r"(a[3]), "r"(b[0]), "r"(b[1]));
}
__device__ __forceinline__ void ldsm_x4(unsigned* r, uint32_t addr) {
    asm volatile("ldmatrix.sync.aligned.m8n8.x4.shared.b16 {%0,%1,%2,%3}, [%4];"
        : "=r"(r[0]), "=r"(r[1]), "=r"(r[2]), "=r"(r[3]) : "r"(addr));
}

// ---------------- K0 (x2): mlp_w fp32 -> bf16 padded ----------------
__global__ void k_convert(const float* __restrict__ w, int eOff, int eCnt) {
    int i = blockIdx.x * 256 + threadIdx.x;
    if (i >= eCnt * 52) return;
    int e = eOff + i / 52, q = i % 52;
    uint2 val;
    if (q < 50) {
        float4 f = *(const float4*)(w + (size_t)e * H_ + 4 * q);
        __nv_bfloat162 lo = __floats2bfloat162_rn(f.x, f.y);
        __nv_bfloat162 hi = __floats2bfloat162_rn(f.z, f.w);
        val.x = *(unsigned*)&lo;
        val.y = *(unsigned*)&hi;
    } else {
        val.x = 0u; val.y = 0u;
    }
    ((uint2*)g_wb)[(size_t)e * 52 + q] = val;
}

// ---------------- K-proj: X = gather(embeds) @ Ws^T + b   (bf16 mma) ----------------
// M = 25600 (b,n rows), N = 200 (pad 224), K = 128. Tile: M=128 per block, full N.
// 16 warps: 8(m) x 2(n); per warp 16 rows x 112 cols (14 n-steps).
#define PROJ_SMEM ((128 * PSTR + 224 * PSTR) * 2 + 224 * 4)

__global__ void __launch_bounds__(512) k_proj(
    const int* __restrict__ idx, const float* __restrict__ emb,
    const float* __restrict__ Ws_w, const float* __restrict__ Ws_b)
{
    extern __shared__ __align__(16) char psm[];
    __nv_bfloat16* sA = (__nv_bfloat16*)psm;          // [128][PSTR] gathered embeds
    __nv_bfloat16* sB = sA + 128 * PSTR;              // [224][PSTR] Ws (rows 200+ garbage, unused cols)
    float* sBias = (float*)(sB + 224 * PSTR);         // [224]

    const int tid = threadIdx.x;
    const int m0 = blockIdx.x * 128;

    if (tid < 224) sBias[tid] = (tid < H_) ? Ws_b[tid] : 0.f;
    // gather A: 128 rows x 32 float4-chunks
    for (int i = tid; i < 128 * 32; i += 512) {
        int r = i >> 5, c4 = i & 31;
        int e = idx[m0 + r];
        float4 f = *(const float4*)(emb + (size_t)e * D_ + 4 * c4);
        __nv_bfloat162 lo = __floats2bfloat162_rn(f.x, f.y);
        __nv_bfloat162 hi = __floats2bfloat162_rn(f.z, f.w);
        uint2 v; v.x = *(unsigned*)&lo; v.y = *(unsigned*)&hi;
        ((uint2*)(sA + r * PSTR))[c4] = v;
    }
    // B: Ws_w [200][128]
    for (int i = tid; i < 200 * 32; i += 512) {
        int r = i >> 5, c4 = i & 31;
        float4 f = *(const float4*)(Ws_w + r * D_ + 4 * c4);
        __nv_bfloat162 lo = __floats2bfloat162_rn(f.x, f.y);
        __nv_bfloat162 hi = __floats2bfloat162_rn(f.z, f.w);
        uint2 v; v.x = *(unsigned*)&lo; v.y = *(unsigned*)&hi;
        ((uint2*)(sB + r * PSTR))[c4] = v;
    }
    __syncthreads();

    const int lane = tid & 31, warp = tid >> 5;
    const int gid = lane >> 2, tig = lane & 3;
    const int wm = warp & 7, wn = warp >> 3;          // 8(m) x 2(n)

    const uint32_t sA_u = smem_u32(sA), sB_u = smem_u32(sB);
    const uint32_t aAddr = sA_u + (uint32_t)(((wm * 16 + (lane & 15)) * PSTR + (lane >> 4) * 8) * 2);
    uint32_t bAddr[7];
#pragma unroll
    for (int j = 0; j < 7; j++)
        bAddr[j] = sB_u + (uint32_t)(((wn * 112 + j * 16 + (lane & 7) + ((lane >> 4) & 1) * 8) * PSTR
                                     + ((lane >> 3) & 1) * 8) * 2);

    float acc[14][4];
#pragma unroll
    for (int ni = 0; ni < 14; ni++)
#pragma unroll
        for (int q = 0; q < 4; q++) acc[ni][q] = 0.f;

#pragma unroll
    for (int ks = 0; ks < 8; ks++) {
        const uint32_t koff = ks * 32u;
        unsigned a[4];
        ldsm_x4(a, aAddr + koff);
#pragma unroll
        for (int j = 0; j < 7; j++) {
            unsigned bb[4];
            ldsm_x4(bb, bAddr[j] + koff);
            mma16816(acc[2 * j],     a, bb + 0);
            mma16816(acc[2 * j + 1], a, bb + 2);
        }
    }

    // store X rows (fp32, +bias); cols >= 200 dropped
    const int r0 = m0 + wm * 16 + gid;
#pragma unroll
    for (int ni = 0; ni < 14; ni++) {
        int c = wn * 112 + ni * 8 + 2 * tig;
        if (c < H_) {
            float b0 = sBias[c], b1 = sBias[c + 1];
            float2 v0, v1;
            v0.x = acc[ni][0] + b0; v0.y = acc[ni][1] + b1;
            v1.x = acc[ni][2] + b0; v1.y = acc[ni][3] + b1;
            *(float2*)(g_x + (size_t)r0 * H_ + c)       = v0;
            *(float2*)(g_x + (size_t)(r0 + 8) * H_ + c) = v1;
        }
    }
}

// ---------------- K1: routing only (256 threads, 41.6 KB static smem) ----------------
__global__ void __launch_bounds__(256) k_routing(
    const int* __restrict__ idx, const int* __restrict__ times)
{
    __shared__ float sU[50 * 200];
    __shared__ float sB[50], sC[50], sV[200], sTmp[50], sRed[9];
    __shared__ int   sIdx[50];

    const int tid = threadIdx.x;
    const int lane = tid & 31, wid = tid >> 5;   // 8 warps
    const int row = blockIdx.x;

    if (tid < 50) {
        sIdx[tid] = idx[row * N_ + tid];
        sB[tid] = 2.0f / (1.0f + (float)times[row * N_ + tid]);
    }
    // copy this row's X slice: rows row*50..row*50+49 are contiguous
    {
        const float4* src = (const float4*)(g_x + (size_t)row * (N_ * H_));
        for (int i = tid; i < (N_ * H_) / 4; i += 256) ((float4*)sU)[i] = src[i];
    }
    __syncthreads();

    // L2 normalize each of the 50 u rows over H
    for (int n = wid; n < 50; n += 8) {
        float ss = 0.f;
        for (int h = lane; h < H_; h += 32) { float v = sU[n * H_ + h]; ss += v * v; }
#pragma unroll
        for (int o = 16; o > 0; o >>= 1) ss += __shfl_xor_sync(0xffffffffu, ss, o);
        float inv = 1.0f / fmaxf(sqrtf(ss), 1e-12f);
        for (int h = lane; h < H_; h += 32) sU[n * H_ + h] *= inv;
    }
    __syncthreads();

    for (int r = 0; r < 3; r++) {
        if (wid == 0) {
            float v0 = (lane < 50) ? sB[lane] : -1e30f;
            float v1 = (lane + 32 < 50) ? sB[lane + 32] : -1e30f;
            float m = fmaxf(v0, v1);
#pragma unroll
            for (int o = 16; o > 0; o >>= 1) m = fmaxf(m, __shfl_xor_sync(0xffffffffu, m, o));
            float e0 = (lane < 50) ? expf(v0 - m) : 0.f;
            float e1 = (lane + 32 < 50) ? expf(v1 - m) : 0.f;
            float s = e0 + e1;
#pragma unroll
            for (int o = 16; o > 0; o >>= 1) s += __shfl_xor_sync(0xffffffffu, s, o);
            float sc = 50.0f / s;
            if (lane < 50) sC[lane] = e0 * sc;
            if (lane + 32 < 50) sC[lane + 32] = e1 * sc;
        }
        __syncthreads();
        float mysq = 0.f;
        if (tid < H_) {
            float sv = 0.f;
#pragma unroll 5
            for (int n = 0; n < 50; n++) sv += sC[n] * sU[n * H_ + tid];
            sV[tid] = sv;
            mysq = sv * sv;
        }
#pragma unroll
        for (int o = 16; o > 0; o >>= 1) mysq += __shfl_xor_sync(0xffffffffu, mysq, o);
        if (lane == 0) sRed[wid] = mysq;
        __syncthreads();
        if (tid == 0) {
            float sq = 0.f;
#pragma unroll
            for (int i = 0; i < 8; i++) sq += sRed[i];
            sRed[8] = sq / ((1.0f + sq) * sqrtf(sq + 1e-9f));
        }
        __syncthreads();
        if (tid < H_) sV[tid] *= sRed[8];
        __syncthreads();
        if (r < 2) {
            for (int n = wid; n < 50; n += 8) {
                float dot = 0.f;
                for (int h = lane; h < H_; h += 32) dot += sU[n * H_ + h] * sV[h];
#pragma unroll
                for (int o = 16; o > 0; o >>= 1) dot += __shfl_xor_sync(0xffffffffu, dot, o);
                if (lane == 0) sB[n] += dot;
            }
            __syncthreads();
        }
    }

    if (tid < H_) {
        float v = sV[tid];
        g_v[row * H_ + tid] = v;
        g_vb[row * KPAD + tid] = __float2bfloat16(v);
    } else if (tid < KPAD) {
        g_vb[row * KPAD + tid] = __float2bfloat16(0.f);
    }

    if (tid < 50) {
        int my = sIdx[tid];
        bool first = true;
        float cs = 0.f;
        for (int m = 0; m < 50; m++) {
            if (sIdx[m] == my) {
                cs += sC[m];
                if (m < tid) first = false;
            }
        }
        sTmp[tid] = first ? cs : -1.0f;
    }
    __syncthreads();
    if (tid == 0) {
        float mp = -1e30f; int K = 0;
        for (int n = 0; n < 50; n++)
            if (sTmp[n] >= 0.f) { K++; mp = fmaxf(mp, sTmp[n]); }
        float Zp = (float)(E_ - K) * expf(-mp);
        for (int n = 0; n < 50; n++)
            if (sTmp[n] >= 0.f) Zp += expf(sTmp[n] - mp);
        int slot = 0;
        for (int n = 0; n < 50; n++)
            if (sTmp[n] >= 0.f) {
                g_fix_id[row * N_ + slot] = sIdx[n];
                g_fix_p[row * N_ + slot] = 0.5f * expf(sTmp[n] - mp) / Zp;
                slot++;
            }
        g_fix_cnt[row] = K;
        g_pbase[row] = 0.5f * expf(-mp) / Zp;
    }
}

// ---------------- K2: decoder bf16 mma GEMM: half scores + exp partials ----------------
#define GEMM_DSMEM ((GBM + GBN) * SAS * 2 + 512)

__global__ void __launch_bounds__(512) k_gemm(const float* __restrict__ mlp_b)
{
    extern __shared__ __align__(16) char gsm[];
    __nv_bfloat16* sA   = (__nv_bfloat16*)gsm;
    __nv_bfloat16* sBm  = sA + GBM * SAS;
    float*         sBias= (float*)(sBm + GBN * SAS);
    float (*s_part)[16] = (float (*)[16])gsm;

    const int tid = threadIdx.x;
    const int eBase = blockIdx.x * GBN;
    const int rBase = blockIdx.y * GBM;

    if (tid < GBN) {
        int e = eBase + tid;
        sBias[tid] = (e < E_) ? mlp_b[e] : 0.f;
    }
    const uint2* gv = (const uint2*)g_vb;
    for (int i = tid; i < GBM * 52; i += 512) {
        int r = i / 52, c = i - r * 52;
        ((uint2*)(sA + r * SAS))[c] = gv[(size_t)(rBase + r) * 52 + c];
    }
    const uint2* gw = (const uint2*)g_wb;
    for (int i = tid; i < GBN * 52; i += 512) {
        int r = i / 52, c = i - r * 52;
        int e = eBase + r;
        uint2 z; z.x = 0u; z.y = 0u;
        ((uint2*)(sBm + r * SAS))[c] = (e < E_) ? gw[(size_t)e * 52 + c] : z;
    }
    __syncthreads();

    const int lane = tid & 31, warp = tid >> 5;
    const int gid = lane >> 2, tig = lane & 3;
    const int wm = warp & 3, wn = warp >> 2;

    const uint32_t sA_u = smem_u32(sA), sB_u = smem_u32(sBm);
    uint32_t aAddr0 = sA_u + (uint32_t)(((wm * 32 + (lane & 15)) * SAS + ((lane >> 4) * 8)) * 2);
    uint32_t aAddr1 = aAddr0 + 16u * SAS * 2u;
    uint32_t bAddr0 = sB_u + (uint32_t)(((wn * 32 + (lane & 7) + (((lane >> 4) & 1) * 8)) * SAS
                                        + (((lane >> 3) & 1) * 8)) * 2);
    uint32_t bAddr1 = bAddr0 + 16u * SAS * 2u;

    float acc[2][4][4];
#pragma unroll
    for (int mi = 0; mi < 2; mi++)
#pragma unroll
        for (int ni = 0; ni < 4; ni++)
#pragma unroll
            for (int q = 0; q < 4; q++) acc[mi][ni][q] = 0.f;

#pragma unroll
    for (int ks = 0; ks < 13; ks++) {
        const uint32_t koff = ks * 32u;
        unsigned a0[4], a1[4], b0[4], b1[4];
        ldsm_x4(a0, aAddr0 + koff);
        ldsm_x4(a1, aAddr1 + koff);
        ldsm_x4(b0, bAddr0 + koff);
        ldsm_x4(b1, bAddr1 + koff);
        mma16816(acc[0][0], a0, b0 + 0);
        mma16816(acc[0][1], a0, b0 + 2);
        mma16816(acc[0][2], a0, b1 + 0);
        mma16816(acc[0][3], a0, b1 + 2);
        mma16816(acc[1][0], a1, b0 + 0);
        mma16816(acc[1][1], a1, b0 + 2);
        mma16816(acc[1][2], a1, b1 + 0);
        mma16816(acc[1][3], a1, b1 + 2);
    }

    float rs[2][2] = {{0.f, 0.f}, {0.f, 0.f}};
#pragma unroll
    for (int mi = 0; mi < 2; mi++) {
        int r0 = rBase + wm * 32 + mi * 16 + gid;
#pragma unroll
        for (int ni = 0; ni < 4; ni++) {
            int ec = wn * 32 + ni * 8 + 2 * tig;
            int e0 = eBase + ec;
            if (e0 < E_) {
                float b0 = sBias[ec], b1 = sBias[ec + 1];
                float s00 = acc[mi][ni][0] + b0;
                float s01 = acc[mi][ni][1] + b1;
                float s10 = acc[mi][ni][2] + b0;
                float s11 = acc[mi][ni][3] + b1;
                *(__half2*)(g_sc + (size_t)r0 * E_ + e0)       = __floats2half2_rn(s00, s01);
                *(__half2*)(g_sc + (size_t)(r0 + 8) * E_ + e0) = __floats2half2_rn(s10, s11);
                rs[mi][0] += __expf(s00) + __expf(s01);
                rs[mi][1] += __expf(s10) + __expf(s11);
            }
        }
    }
    __syncthreads();
    const int slot = wn * 4 + tig;
#pragma unroll
    for (int mi = 0; mi < 2; mi++) {
        s_part[wm * 32 + mi * 16 + gid][slot]     = rs[mi][0];
        s_part[wm * 32 + mi * 16 + gid + 8][slot] = rs[mi][1];
    }
    __syncthreads();
    if (tid < GBM) {
        float s = 0.f;
#pragma unroll
        for (int j = 0; j < 16; j++) s += s_part[tid][j];
        g_part[(size_t)(rBase + tid) * NPART + blockIdx.x] = s;
    }
}

// ---------------- K3: reduce partials -> 0.5/Z_s ----------------
__global__ void __launch_bounds__(128) k_reduce() {
    __shared__ float red[128];
    const int row = blockIdx.x, tid = threadIdx.x;
    float s = 0.f;
    for (int p = tid; p < NPART; p += 128) s += g_part[(size_t)row * NPART + p];
    red[tid] = s;
    __syncthreads();
    for (int o = 64; o > 0; o >>= 1) {
        if (tid < o) red[tid] += red[tid + o];
        __syncthreads();
    }
    if (tid == 0) g_invZs[row] = 0.5f / red[0];
}

// ---------------- K4: fixup values at history ids (fp32 dot) ----------------
__global__ void __launch_bounds__(256) k_fixdot(const float* __restrict__ mlp_w,
                                                const float* __restrict__ mlp_b) {
    const int row = blockIdx.x;
    const int warp = threadIdx.x >> 5, lane = threadIdx.x & 31;
    const int cnt = g_fix_cnt[row];
    for (int slot = warp; slot < cnt; slot += 8) {
        int id = g_fix_id[row * N_ + slot];
        float dot = 0.f;
        for (int h = lane; h < H_; h += 32)
            dot += g_v[row * H_ + h] * mlp_w[(size_t)id * H_ + h];
#pragma unroll
        for (int o = 16; o > 0; o >>= 1) dot += __shfl_xor_sync(0xffffffffu, dot, o);
        if (lane == 0) {
            float s = dot + mlp_b[id];
            g_fix_p[row * N_ + slot] =
                __logf(g_fix_p[row * N_ + slot] + g_invZs[row] * __expf(s));
        }
    }
}

// ---------------- K5: finalize from half scores ----------------
__global__ void __launch_bounds__(256) k_finalize(float* __restrict__ out) {
    const int row = blockIdx.y;
    const int q = blockIdx.x * 256 + threadIdx.x;
    if (q >= E_ / 4) return;
    uint2 packed = *(const uint2*)(g_sc + (size_t)row * E_ + 4 * q);
    __half2 h0 = *(__half2*)&packed.x;
    __half2 h1 = *(__half2*)&packed.y;
    float2 f0 = __half22float2(h0);
    float2 f1 = __half22float2(h1);
    const float pb = g_pbase[row], iz = g_invZs[row];
    float4 v;
    v.x = __logf(pb + iz * __expf(f0.x));
    v.y = __logf(pb + iz * __expf(f0.y));
    v.z = __logf(pb + iz * __expf(f1.x));
    v.w = __logf(pb + iz * __expf(f1.y));
    *(float4*)(out + (size_t)row * E_ + 4 * q) = v;
}

// ---------------- K6: write fixed values for history ids ----------------
__global__ void k_fix_post(float* __restrict__ out) {
    const int row = blockIdx.x, t = threadIdx.x;
    if (t < g_fix_cnt[row]) {
        int id = g_fix_id[row * N_ + t];
        out[(size_t)row * E_ + id] = g_fix_p[row * N_ + t];
    }
}

// ---------------- launch ----------------
extern "C" void kernel_launch(void* const* d_in, const int* in_sizes, int n_in,
                              void* d_out, int out_size) {
    const int*   idx   = (const int*)d_in[0];
    const int*   times = (const int*)d_in[1];
    const float* emb   = (const float*)d_in[2];
    const float* Ws_w  = (const float*)d_in[3];
    const float* Ws_b  = (const float*)d_in[4];
    const float* mlp_w = (const float*)d_in[5];
    const float* mlp_b = (const float*)d_in[6];
    float* out = (float*)d_out;

    static bool attr_done = false;
    if (!attr_done) {
        cudaFuncSetAttribute(k_proj, cudaFuncAttributeMaxDynamicSharedMemorySize, PROJ_SMEM);
        cudaFuncSetAttribute(k_gemm, cudaFuncAttributeMaxDynamicSharedMemorySize, GEMM_DSMEM);
        attr_done = true;
    }

    // 2 convert launches + proj => my launch #3 (process #5) = k_routing for ncu
    const int eHalf = E_ / 2;
    k_convert<<<(eHalf * 52 + 255) / 256, 256>>>(mlp_w, 0, eHalf);
    k_convert<<<(eHalf * 52 + 255) / 256, 256>>>(mlp_w, eHalf, E_ - eHalf);
    k_proj<<<(B_ * N_) / 128, 512, PROJ_SMEM>>>(idx, emb, Ws_w, Ws_b);
    k_routing<<<B_, 256>>>(idx, times);
    dim3 gg(NPART, B_ / GBM);
    k_gemm<<<gg, 512, GEMM_DSMEM>>>(mlp_b);
    k_reduce<<<B_, 128>>>();
    k_fixdot<<<B_, 256>>>(mlp_w, mlp_b);
    dim3 gf((E_ / 4 + 255) / 256, B_);
    k_finalize<<<gf, 256>>>(out);
    k_fix_post<<<B_, 64>>>(out);
}

// round 8
// speedup vs baseline: 2.0281x; 1.2621x over previous
#include <cuda_runtime.h>
#include <cuda_bf16.h>
#include <cuda_fp16.h>
#include <cstdint>

#define B_    512
#define N_    50
#define D_    128
#define H_    200
#define E_    50000
#define EPAD  50048         // 391*128 — padded entity rows (zero-init tail)
#define KPAD  208           // H_ padded to 13*16 for decoder mma
#define GBM   128
#define GBN   128
#define NPART 391           // EPAD/GBN
#define SAS   216           // decoder gemm smem stride (bf16 elems)
#define PSTR  136           // projection gemm smem stride (bf16)

// ---------------- static device scratch ----------------
__device__ __nv_bfloat16 g_wb[(size_t)EPAD * KPAD];    // mlp_w bf16, padded (20.8 MB; tail zero)
__device__ __align__(16) __half g_sc[(size_t)B_ * E_]; // fp16 scores (51.2 MB)
__device__ __align__(16) float g_x[(size_t)B_ * N_ * H_]; // projected x (20.5 MB)
__device__ __nv_bfloat16 g_vb[B_ * KPAD];              // poses bf16, K-padded
__device__ float g_v[B_ * H_];                         // poses fp32 (for fixdot)
__device__ float g_part[(size_t)B_ * NPART];           // per-(row, e-block) exp partials
__device__ float g_invZs[B_];                          // 0.5 / Z_s
__device__ float g_pbase[B_];                          // 0.5 * exp(-m_p) / Z_p
__device__ float g_fix_p[B_ * N_];
__device__ int   g_fix_id[B_ * N_];
__device__ int   g_fix_cnt[B_];

// ---------------- shared PTX helpers ----------------
__device__ __forceinline__ uint32_t smem_u32(const void* p) {
    uint32_t a;
    asm("{ .reg .u64 t; cvta.to.shared.u64 t, %1; cvt.u32.u64 %0, t; }" : "=r"(a) : "l"(p));
    return a;
}
__device__ __forceinline__ void mma16816(float* c, const unsigned* a, const unsigned* b) {
    asm volatile("mma.sync.aligned.m16n8k16.row.col.f32.bf16.bf16.f32 "
        "{%0,%1,%2,%3}, {%4,%5,%6,%7}, {%8,%9}, {%0,%1,%2,%3};"
        : "+f"(c[0]), "+f"(c[1]), "+f"(c[2]), "+f"(c[3])
        : "r"(a[0]), "r"(a[1]), "r"(a[2]), "r"(a[3]), "r"(b[0]), "r"(b[1]));
}
__device__ __forceinline__ void ldsm_x4(unsigned* r, uint32_t addr) {
    asm volatile("ldmatrix.sync.aligned.m8n8.x4.shared.b16 {%0,%1,%2,%3}, [%4];"
        : "=r"(r[0]), "=r"(r[1]), "=r"(r[2]), "=r"(r[3]) : "r"(addr));
}
__device__ __forceinline__ void cp16(uint32_t dst, const void* src) {
    asm volatile("cp.async.cg.shared.global [%0], [%1], 16;" :: "r"(dst), "l"(src));
}
#define CP_COMMIT() asm volatile("cp.async.commit_group;")
#define CP_WAIT0()  asm volatile("cp.async.wait_group 0;" ::: "memory")

// ---------------- K-conv: mlp_w fp32 -> bf16 padded ----------------
__global__ void k_convert(const float* __restrict__ w) {
    int i = blockIdx.x * 256 + threadIdx.x;        // uint2 (4 bf16) index
    if (i >= E_ * 52) return;
    int e = i / 52, q = i % 52;
    uint2 val;
    if (q < 50) {
        float4 f = *(const float4*)(w + (size_t)e * H_ + 4 * q);
        __nv_bfloat162 lo = __floats2bfloat162_rn(f.x, f.y);
        __nv_bfloat162 hi = __floats2bfloat162_rn(f.z, f.w);
        val.x = *(unsigned*)&lo;
        val.y = *(unsigned*)&hi;
    } else {
        val.x = 0u; val.y = 0u;
    }
    ((uint2*)g_wb)[(size_t)e * 52 + q] = val;
}

// ---------------- K-proj: X = gather(embeds) @ Ws^T + b   (bf16 mma) ----------------
#define PROJ_SMEM ((128 * PSTR + 224 * PSTR) * 2 + 224 * 4)

__global__ void __launch_bounds__(512) k_proj(
    const int* __restrict__ idx, const float* __restrict__ emb,
    const float* __restrict__ Ws_w, const float* __restrict__ Ws_b)
{
    extern __shared__ __align__(16) char psm[];
    __nv_bfloat16* sA = (__nv_bfloat16*)psm;          // [128][PSTR]
    __nv_bfloat16* sB = sA + 128 * PSTR;              // [224][PSTR]
    float* sBias = (float*)(sB + 224 * PSTR);         // [224]

    const int tid = threadIdx.x;
    const int m0 = blockIdx.x * 128;

    if (tid < 224) sBias[tid] = (tid < H_) ? Ws_b[tid] : 0.f;
    for (int i = tid; i < 128 * 32; i += 512) {
        int r = i >> 5, c4 = i & 31;
        int e = idx[m0 + r];
        float4 f = *(const float4*)(emb + (size_t)e * D_ + 4 * c4);
        __nv_bfloat162 lo = __floats2bfloat162_rn(f.x, f.y);
        __nv_bfloat162 hi = __floats2bfloat162_rn(f.z, f.w);
        uint2 v; v.x = *(unsigned*)&lo; v.y = *(unsigned*)&hi;
        ((uint2*)(sA + r * PSTR))[c4] = v;
    }
    for (int i = tid; i < 200 * 32; i += 512) {
        int r = i >> 5, c4 = i & 31;
        float4 f = *(const float4*)(Ws_w + r * D_ + 4 * c4);
        __nv_bfloat162 lo = __floats2bfloat162_rn(f.x, f.y);
        __nv_bfloat162 hi = __floats2bfloat162_rn(f.z, f.w);
        uint2 v; v.x = *(unsigned*)&lo; v.y = *(unsigned*)&hi;
        ((uint2*)(sB + r * PSTR))[c4] = v;
    }
    __syncthreads();

    const int lane = tid & 31, warp = tid >> 5;
    const int gid = lane >> 2, tig = lane & 3;
    const int wm = warp & 7, wn = warp >> 3;

    const uint32_t sA_u = smem_u32(sA), sB_u = smem_u32(sB);
    const uint32_t aAddr = sA_u + (uint32_t)(((wm * 16 + (lane & 15)) * PSTR + (lane >> 4) * 8) * 2);
    uint32_t bAddr[7];
#pragma unroll
    for (int j = 0; j < 7; j++)
        bAddr[j] = sB_u + (uint32_t)(((wn * 112 + j * 16 + (lane & 7) + ((lane >> 4) & 1) * 8) * PSTR
                                     + ((lane >> 3) & 1) * 8) * 2);

    float acc[14][4];
#pragma unroll
    for (int ni = 0; ni < 14; ni++)
#pragma unroll
        for (int q = 0; q < 4; q++) acc[ni][q] = 0.f;

#pragma unroll
    for (int ks = 0; ks < 8; ks++) {
        const uint32_t koff = ks * 32u;
        unsigned a[4];
        ldsm_x4(a, aAddr + koff);
#pragma unroll
        for (int j = 0; j < 7; j++) {
            unsigned bb[4];
            ldsm_x4(bb, bAddr[j] + koff);
            mma16816(acc[2 * j],     a, bb + 0);
            mma16816(acc[2 * j + 1], a, bb + 2);
        }
    }

    const int r0 = m0 + wm * 16 + gid;
#pragma unroll
    for (int ni = 0; ni < 14; ni++) {
        int c = wn * 112 + ni * 8 + 2 * tig;
        if (c < H_) {
            float b0 = sBias[c], b1 = sBias[c + 1];
            float2 v0, v1;
            v0.x = acc[ni][0] + b0; v0.y = acc[ni][1] + b1;
            v1.x = acc[ni][2] + b0; v1.y = acc[ni][3] + b1;
            *(float2*)(g_x + (size_t)r0 * H_ + c)       = v0;
            *(float2*)(g_x + (size_t)(r0 + 8) * H_ + c) = v1;
        }
    }
}

// ---------------- K1: routing (256 thr, 4+ blocks/SM, fused gather+normalize) ----------------
__global__ void __launch_bounds__(256, 4) k_routing(
    const int* __restrict__ idx, const int* __restrict__ times)
{
    __shared__ __align__(16) float sU[50 * 200];
    __shared__ float sB[50], sC[50], sV[200], sTmp[50], sRed[8];
    __shared__ int   sIdx[50];

    const int tid = threadIdx.x;
    const int lane = tid & 31, wid = tid >> 5;   // 8 warps
    const int row = blockIdx.x;

    if (tid < 50) {
        sIdx[tid] = idx[row * N_ + tid];
        sB[tid] = 2.0f / (1.0f + (float)times[row * N_ + tid]);
    }

    // fused gather + L2 normalize: one warp per u-row, values stay in registers
    for (int n = wid; n < 50; n += 8) {
        const float4* src = (const float4*)(g_x + ((size_t)row * N_ + n) * H_);
        float4 f0 = src[lane];
        float ss = f0.x * f0.x + f0.y * f0.y + f0.z * f0.z + f0.w * f0.w;
        float4 f1;
        const bool has2 = lane < 18;               // 50 float4 per row
        if (has2) {
            f1 = src[32 + lane];
            ss += f1.x * f1.x + f1.y * f1.y + f1.z * f1.z + f1.w * f1.w;
        }
#pragma unroll
        for (int o = 16; o > 0; o >>= 1) ss += __shfl_xor_sync(0xffffffffu, ss, o);
        float inv = 1.0f / fmaxf(sqrtf(ss), 1e-12f);
        float4* dst = (float4*)(sU + n * 200);
        f0.x *= inv; f0.y *= inv; f0.z *= inv; f0.w *= inv;
        dst[lane] = f0;
        if (has2) {
            f1.x *= inv; f1.y *= inv; f1.z *= inv; f1.w *= inv;
            dst[32 + lane] = f1;
        }
    }
    __syncthreads();

    for (int r = 0; r < 3; r++) {
        // softmax(b)*N -> c  (warp 0)
        if (wid == 0) {
            float v0 = (lane < 50) ? sB[lane] : -1e30f;
            float v1 = (lane + 32 < 50) ? sB[lane + 32] : -1e30f;
            float m = fmaxf(v0, v1);
#pragma unroll
            for (int o = 16; o > 0; o >>= 1) m = fmaxf(m, __shfl_xor_sync(0xffffffffu, m, o));
            float e0 = (lane < 50) ? expf(v0 - m) : 0.f;
            float e1 = (lane + 32 < 50) ? expf(v1 - m) : 0.f;
            float s = e0 + e1;
#pragma unroll
            for (int o = 16; o > 0; o >>= 1) s += __shfl_xor_sync(0xffffffffu, s, o);
            float sc = 50.0f / s;
            if (lane < 50) sC[lane] = e0 * sc;
            if (lane + 32 < 50) sC[lane + 32] = e1 * sc;
        }
        __syncthreads();

        // s = sum_n c_n u_n  (threads 0..199), keep in register
        float sv = 0.f, mysq = 0.f;
        if (tid < H_) {
#pragma unroll 5
            for (int n = 0; n < 50; n++) sv += sC[n] * sU[n * H_ + tid];
            mysq = sv * sv;
        }
#pragma unroll
        for (int o = 16; o > 0; o >>= 1) mysq += __shfl_xor_sync(0xffffffffu, mysq, o);
        if (lane == 0) sRed[wid] = mysq;
        __syncthreads();

        // every thread computes squash scale (no extra barrier)
        float sq = 0.f;
#pragma unroll
        for (int i = 0; i < 8; i++) sq += sRed[i];
        float scale = sq / ((1.0f + sq) * sqrtf(sq + 1e-9f));
        if (tid < H_) sV[tid] = sv * scale;
        __syncthreads();

        if (r < 2) {
            for (int n = wid; n < 50; n += 8) {
                float dot = 0.f;
                for (int h = lane; h < H_; h += 32) dot += sU[n * H_ + h] * sV[h];
#pragma unroll
                for (int o = 16; o > 0; o >>= 1) dot += __shfl_xor_sync(0xffffffffu, dot, o);
                if (lane == 0) sB[n] += dot;
            }
            __syncthreads();
        }
    }

    if (tid < H_) {
        float v = sV[tid];
        g_v[row * H_ + tid] = v;
        g_vb[row * KPAD + tid] = __float2bfloat16(v);
    } else if (tid < KPAD) {
        g_vb[row * KPAD + tid] = __float2bfloat16(0.f);
    }

    if (tid < 50) {
        int my = sIdx[tid];
        bool first = true;
        float cs = 0.f;
        for (int m = 0; m < 50; m++) {
            if (sIdx[m] == my) {
                cs += sC[m];
                if (m < tid) first = false;
            }
        }
        sTmp[tid] = first ? cs : -1.0f;
    }
    __syncthreads();
    if (tid == 0) {
        float mp = -1e30f; int K = 0;
        for (int n = 0; n < 50; n++)
            if (sTmp[n] >= 0.f) { K++; mp = fmaxf(mp, sTmp[n]); }
        float Zp = (float)(E_ - K) * expf(-mp);
        for (int n = 0; n < 50; n++)
            if (sTmp[n] >= 0.f) Zp += expf(sTmp[n] - mp);
        int slot = 0;
        for (int n = 0; n < 50; n++)
            if (sTmp[n] >= 0.f) {
                g_fix_id[row * N_ + slot] = sIdx[n];
                g_fix_p[row * N_ + slot] = 0.5f * expf(sTmp[n] - mp) / Zp;
                slot++;
            }
        g_fix_cnt[row] = K;
        g_pbase[row] = 0.5f * expf(-mp) / Zp;
    }
}

// ---------------- K2: decoder bf16 mma GEMM (cp.async loads) ----------------
#define GEMM_DSMEM ((GBM + GBN) * SAS * 2 + 512)

__global__ void __launch_bounds__(512) k_gemm(const float* __restrict__ mlp_b)
{
    extern __shared__ __align__(16) char gsm[];
    __nv_bfloat16* sA   = (__nv_bfloat16*)gsm;
    __nv_bfloat16* sBm  = sA + GBM * SAS;
    float*         sBias= (float*)(sBm + GBN * SAS);
    float (*s_part)[16] = (float (*)[16])gsm;

    const int tid = threadIdx.x;
    const int eBase = blockIdx.x * GBN;
    const int rBase = blockIdx.y * GBM;

    if (tid < GBN) {
        int e = eBase + tid;
        sBias[tid] = (e < E_) ? mlp_b[e] : 0.f;
    }
    // cp.async tile loads: 26 x 16B chunks per row, no guards (EPAD pad rows are zero)
    {
        const uint32_t sA_b = smem_u32(sA), sB_b = smem_u32(sBm);
        const char* srcA = (const char*)g_vb + (size_t)rBase * KPAD * 2;
        const char* srcB = (const char*)g_wb + (size_t)eBase * KPAD * 2;
        for (int i = tid; i < GBM * 26; i += 512) {
            int r = i / 26, c = i - r * 26;
            cp16(sA_b + (uint32_t)(r * (SAS * 2) + c * 16), srcA + (size_t)r * 416 + c * 16);
        }
        for (int i = tid; i < GBN * 26; i += 512) {
            int r = i / 26, c = i - r * 26;
            cp16(sB_b + (uint32_t)(r * (SAS * 2) + c * 16), srcB + (size_t)r * 416 + c * 16);
        }
        CP_COMMIT();
        CP_WAIT0();
    }
    __syncthreads();

    const int lane = tid & 31, warp = tid >> 5;
    const int gid = lane >> 2, tig = lane & 3;
    const int wm = warp & 3, wn = warp >> 2;

    const uint32_t sA_u = smem_u32(sA), sB_u = smem_u32(sBm);
    uint32_t aAddr0 = sA_u + (uint32_t)(((wm * 32 + (lane & 15)) * SAS + ((lane >> 4) * 8)) * 2);
    uint32_t aAddr1 = aAddr0 + 16u * SAS * 2u;
    uint32_t bAddr0 = sB_u + (uint32_t)(((wn * 32 + (lane & 7) + (((lane >> 4) & 1) * 8)) * SAS
                                        + (((lane >> 3) & 1) * 8)) * 2);
    uint32_t bAddr1 = bAddr0 + 16u * SAS * 2u;

    float acc[2][4][4];
#pragma unroll
    for (int mi = 0; mi < 2; mi++)
#pragma unroll
        for (int ni = 0; ni < 4; ni++)
#pragma unroll
            for (int q = 0; q < 4; q++) acc[mi][ni][q] = 0.f;

#pragma unroll
    for (int ks = 0; ks < 13; ks++) {
        const uint32_t koff = ks * 32u;
        unsigned a0[4], a1[4], b0[4], b1[4];
        ldsm_x4(a0, aAddr0 + koff);
        ldsm_x4(a1, aAddr1 + koff);
        ldsm_x4(b0, bAddr0 + koff);
        ldsm_x4(b1, bAddr1 + koff);
        mma16816(acc[0][0], a0, b0 + 0);
        mma16816(acc[0][1], a0, b0 + 2);
        mma16816(acc[0][2], a0, b1 + 0);
        mma16816(acc[0][3], a0, b1 + 2);
        mma16816(acc[1][0], a1, b0 + 0);
        mma16816(acc[1][1], a1, b0 + 2);
        mma16816(acc[1][2], a1, b1 + 0);
        mma16816(acc[1][3], a1, b1 + 2);
    }

    float rs[2][2] = {{0.f, 0.f}, {0.f, 0.f}};
#pragma unroll
    for (int mi = 0; mi < 2; mi++) {
        int r0 = rBase + wm * 32 + mi * 16 + gid;
#pragma unroll
        for (int ni = 0; ni < 4; ni++) {
            int ec = wn * 32 + ni * 8 + 2 * tig;
            int e0 = eBase + ec;
            if (e0 < E_) {
                float b0 = sBias[ec], b1 = sBias[ec + 1];
                float s00 = acc[mi][ni][0] + b0;
                float s01 = acc[mi][ni][1] + b1;
                float s10 = acc[mi][ni][2] + b0;
                float s11 = acc[mi][ni][3] + b1;
                *(__half2*)(g_sc + (size_t)r0 * E_ + e0)       = __floats2half2_rn(s00, s01);
                *(__half2*)(g_sc + (size_t)(r0 + 8) * E_ + e0) = __floats2half2_rn(s10, s11);
                rs[mi][0] += __expf(s00) + __expf(s01);
                rs[mi][1] += __expf(s10) + __expf(s11);
            }
        }
    }
    __syncthreads();
    const int slot = wn * 4 + tig;
#pragma unroll
    for (int mi = 0; mi < 2; mi++) {
        s_part[wm * 32 + mi * 16 + gid][slot]     = rs[mi][0];
        s_part[wm * 32 + mi * 16 + gid + 8][slot] = rs[mi][1];
    }
    __syncthreads();
    if (tid < GBM) {
        float s = 0.f;
#pragma unroll
        for (int j = 0; j < 16; j++) s += s_part[tid][j];
        g_part[(size_t)(rBase + tid) * NPART + blockIdx.x] = s;
    }
}

// ---------------- K3: reduce partials -> 0.5/Z_s ----------------
__global__ void __launch_bounds__(128) k_reduce() {
    __shared__ float red[128];
    const int row = blockIdx.x, tid = threadIdx.x;
    float s = 0.f;
    for (int p = tid; p < NPART; p += 128) s += g_part[(size_t)row * NPART + p];
    red[tid] = s;
    __syncthreads();
    for (int o = 64; o > 0; o >>= 1) {
        if (tid < o) red[tid] += red[tid + o];
        __syncthreads();
    }
    if (tid == 0) g_invZs[row] = 0.5f / red[0];
}

// ---------------- K4: fixup values at history ids (fp32 dot) ----------------
__global__ void __launch_bounds__(256) k_fixdot(const float* __restrict__ mlp_w,
                                                const float* __restrict__ mlp_b) {
    const int row = blockIdx.x;
    const int warp = threadIdx.x >> 5, lane = threadIdx.x & 31;
    const int cnt = g_fix_cnt[row];
    for (int slot = warp; slot < cnt; slot += 8) {
        int id = g_fix_id[row * N_ + slot];
        float dot = 0.f;
        for (int h = lane; h < H_; h += 32)
            dot += g_v[row * H_ + h] * mlp_w[(size_t)id * H_ + h];
#pragma unroll
        for (int o = 16; o > 0; o >>= 1) dot += __shfl_xor_sync(0xffffffffu, dot, o);
        if (lane == 0) {
            float s = dot + mlp_b[id];
            g_fix_p[row * N_ + slot] =
                __logf(g_fix_p[row * N_ + slot] + g_invZs[row] * __expf(s));
        }
    }
}

// ---------------- K5: finalize from half scores ----------------
__global__ void __launch_bounds__(256) k_finalize(float* __restrict__ out) {
    const int row = blockIdx.y;
    const int q = blockIdx.x * 256 + threadIdx.x;
    if (q >= E_ / 4) return;
    uint2 packed = *(const uint2*)(g_sc + (size_t)row * E_ + 4 * q);
    __half2 h0 = *(__half2*)&packed.x;
    __half2 h1 = *(__half2*)&packed.y;
    float2 f0 = __half22float2(h0);
    float2 f1 = __half22float2(h1);
    const float pb = g_pbase[row], iz = g_invZs[row];
    float4 v;
    v.x = __logf(pb + iz * __expf(f0.x));
    v.y = __logf(pb + iz * __expf(f0.y));
    v.z = __logf(pb + iz * __expf(f1.x));
    v.w = __logf(pb + iz * __expf(f1.y));
    *(float4*)(out + (size_t)row * E_ + 4 * q) = v;
}

// ---------------- K6: write fixed values for history ids ----------------
__global__ void k_fix_post(float* __restrict__ out) {
    const int row = blockIdx.x, t = threadIdx.x;
    if (t < g_fix_cnt[row]) {
        int id = g_fix_id[row * N_ + t];
        out[(size_t)row * E_ + id] = g_fix_p[row * N_ + t];
    }
}

// ---------------- launch ----------------
extern "C" void kernel_launch(void* const* d_in, const int* in_sizes, int n_in,
                              void* d_out, int out_size) {
    const int*   idx   = (const int*)d_in[0];
    const int*   times = (const int*)d_in[1];
    const float* emb   = (const float*)d_in[2];
    const float* Ws_w  = (const float*)d_in[3];
    const float* Ws_b  = (const float*)d_in[4];
    const float* mlp_w = (const float*)d_in[5];
    const float* mlp_b = (const float*)d_in[6];
    float* out = (float*)d_out;

    static bool attr_done = false;
    if (!attr_done) {
        cudaFuncSetAttribute(k_proj, cudaFuncAttributeMaxDynamicSharedMemorySize, PROJ_SMEM);
        cudaFuncSetAttribute(k_gemm, cudaFuncAttributeMaxDynamicSharedMemorySize, GEMM_DSMEM);
        attr_done = true;
    }

    // order: proj, routing, convert, gemm (4th launch -> ncu capture on k_gemm)
    k_proj<<<(B_ * N_) / 128, 512, PROJ_SMEM>>>(idx, emb, Ws_w, Ws_b);
    k_routing<<<B_, 256>>>(idx, times);
    k_convert<<<(E_ * 52 + 255) / 256, 256>>>(mlp_w);
    dim3 gg(NPART, B_ / GBM);
    k_gemm<<<gg, 512, GEMM_DSMEM>>>(mlp_b);
    k_reduce<<<B_, 128>>>();
    k_fixdot<<<B_, 256>>>(mlp_w, mlp_b);
    dim3 gf((E_ / 4 + 255) / 256, B_);
    k_finalize<<<gf, 256>>>(out);
    k_fix_post<<<B_, 64>>>(out);
}